// round 14
// baseline (speedup 1.0000x reference)
#include <cuda_runtime.h>
#include <cuda_fp16.h>
#include <stdint.h>
#include <math.h>

#define MAXN 50016
#define MAXE 800000
#define MAXET (MAXE + MAXN)
#define HCDIM 128
#define NHEAD 4
#define GN 64
#define LINDIM 256
#define OUTDIM 10

#define SROW 136                       // smem row stride in halves (128 + 8 pad)
#define TILE_HALVES (128 * SROW)       // 17408 halves = 34816 B
#define A64_T (64 * SROW)              // 8704 halves
#define SMEM_L12 (3 * TILE_HALVES * 2)             // Ahi + Whi + Wlo = 104448 B
#define SMEM_L0  ((2 * A64_T + 2 * TILE_HALVES) * 2) // = 104448 B

// ---------------- device scratch ----------------
__device__ int   g_counts[MAXN];
__device__ int   g_rowptr[MAXN + 1];
__device__ int   g_woff[MAXN];
__device__ int   g_srcidx[MAXET];
__device__ int   g_bnode[MAXN];
__device__ __align__(16) float g_asrc[MAXN * NHEAD];
__device__ __align__(16) float g_adst[MAXN * NHEAD];
__device__ __half2 g_Hh[MAXN * (HCDIM / 2)];        // GEMM out (gather src)
__device__ __half2 g_Hio[2][MAXN * (HCDIM / 2)];    // layer io
__device__ __half2 g_xhi[MAXN * (HCDIM / 2)];
__device__ __half2 g_xlo[MAXN * (HCDIM / 2)];
__device__ __align__(16) __half g_Whi[3][HCDIM * HCDIM];
__device__ __align__(16) __half g_Wlo[3][HCDIM * HCDIM];
__device__ int   g_bsums[128];

// ---------------- dtype detection helpers ----------------
__device__ __forceinline__ bool edge_is64(const void* edge, long long N) {
    const long long* p = (const long long*)edge;
    int lane = threadIdx.x & 31;
    long long v0 = p[lane];
    long long v1 = p[lane + 32];
    bool bad = (v0 < 0) | (v0 >= N) | (v1 < 0) | (v1 >= N);
    return __all_sync(0xffffffffu, !bad);
}
__device__ __forceinline__ bool batch_is64(const void* batch, int N) {
    const long long* p = (const long long*)batch;
    int lane = threadIdx.x & 31;
    int idx = N / 2 - 1 - lane;
    long long v = (idx >= 0) ? p[idx] : 0;
    bool bad = (v < 0) | (v >= 64);
    return __all_sync(0xffffffffu, !bad);
}

// ---------------- prep: W split + x split (legacy-stream chain) -------------
__global__ void prep_all(const float* __restrict__ x,
                         const float* __restrict__ w0,
                         const float* __restrict__ w1,
                         const float* __restrict__ w2, int N) {
    int idx = blockIdx.x * blockDim.x + threadIdx.x;
    if (idx < 3 * HCDIM * HCDIM) {
        int m = idx >> 14;
        int r = idx & 16383;
        const float* w = (m == 0) ? w0 : (m == 1) ? w1 : w2;
        float v = w[r];
        __half hi = __float2half_rn(v);
        g_Whi[m][r] = hi;
        g_Wlo[m][r] = __float2half_rn(v - __half2float(hi));
    }
    if (idx < N * 32) {
        float4 v = ((const float4*)x)[idx];
        __half h0 = __float2half_rn(v.x);
        __half h1 = __float2half_rn(v.y);
        __half h2 = __float2half_rn(v.z);
        __half h3 = __float2half_rn(v.w);
        __half2 hiA = __halves2half2(h0, h1);
        __half2 hiB = __halves2half2(h2, h3);
        __half2 loA = __halves2half2(__float2half_rn(v.x - __half2float(h0)),
                                     __float2half_rn(v.y - __half2float(h1)));
        __half2 loB = __halves2half2(__float2half_rn(v.z - __half2float(h2)),
                                     __float2half_rn(v.w - __half2float(h3)));
        uint2 sh, sl;
        sh.x = *(const uint32_t*)&hiA;  sh.y = *(const uint32_t*)&hiB;
        sl.x = *(const uint32_t*)&loA;  sl.y = *(const uint32_t*)&loB;
        ((uint2*)g_xhi)[idx] = sh;
        ((uint2*)g_xlo)[idx] = sl;
    }
}

// node init (counts seed + batch convert) — head of the CSR stream chain
__global__ void init_node(const void* batch, int N) {
    bool b64 = batch_is64(batch, N);
    int i = blockIdx.x * blockDim.x + threadIdx.x;
    if (i >= N) return;
    g_counts[i] = 1;
    g_bnode[i] = b64 ? (int)((const long long*)batch)[i]
                     : ((const int*)batch)[i];
}

// histogram over dst, 4 edges/thread, vector loads
__global__ void hist_kernel(const void* edge, int E, int N) {
    bool e64 = edge_is64(edge, (long long)N);
    int base = (blockIdx.x * blockDim.x + threadIdx.x) * 4;
    if (base >= E) return;
    int n = min(4, E - base);
    int dd[4];
    if (e64) {
        const long long* p = (const long long*)edge + E;
        if (n == 4 && (((E + base) & 1) == 0)) {
            longlong2 v0 = *(const longlong2*)(p + base);
            longlong2 v1 = *(const longlong2*)(p + base + 2);
            dd[0] = (int)v0.x; dd[1] = (int)v0.y;
            dd[2] = (int)v1.x; dd[3] = (int)v1.y;
        } else {
            for (int j = 0; j < n; j++) dd[j] = (int)p[base + j];
        }
    } else {
        const int* p = (const int*)edge + E;
        if (n == 4 && (((E + base) & 3) == 0)) {
            int4 v = *(const int4*)(p + base);
            dd[0] = v.x; dd[1] = v.y; dd[2] = v.z; dd[3] = v.w;
        } else {
            for (int j = 0; j < n; j++) dd[j] = p[base + j];
        }
    }
    for (int j = 0; j < n; j++) atomicAdd(&g_counts[dd[j]], 1);
}

__global__ void scan_block(int N) {
    __shared__ int sh[1024];
    int i = blockIdx.x * 1024 + threadIdx.x;
    int v = (i < N) ? g_counts[i] : 0;
    sh[threadIdx.x] = v;
    __syncthreads();
    for (int off = 1; off < 1024; off <<= 1) {
        int x = 0;
        if (threadIdx.x >= off) x = sh[threadIdx.x - off];
        __syncthreads();
        if (threadIdx.x >= off) sh[threadIdx.x] += x;
        __syncthreads();
    }
    if (i < N) g_rowptr[i] = sh[threadIdx.x] - v;
    if (threadIdx.x == 1023) g_bsums[blockIdx.x] = sh[1023];
}

__global__ void scan_add2(int N, int total) {
    __shared__ int off0;
    int chunk = (blockIdx.x * blockDim.x) >> 10;
    if (threadIdx.x == 0) {
        int acc = 0;
        for (int b = 0; b < chunk; b++) acc += g_bsums[b];
        off0 = acc;
    }
    __syncthreads();
    int i = blockIdx.x * blockDim.x + threadIdx.x;
    if (i < N) {
        int r = g_rowptr[i] + off0;
        g_rowptr[i] = r;
        g_woff[i] = r;
    }
    if (i == 0) g_rowptr[N] = total;
}

// scatter: 4 edges/thread with vector loads, then self-loops
__global__ void scatter_kernel(const void* edge, int E, int N) {
    bool e64 = edge_is64(edge, (long long)N);
    int E4 = (E + 3) >> 2;
    int i = blockIdx.x * blockDim.x + threadIdx.x;
    if (i < E4) {
        int base = i * 4;
        int n = min(4, E - base);
        int ss[4], dd[4];
        if (e64) {
            const long long* p = (const long long*)edge;
            if (n == 4 && ((base & 1) == 0) && (((E + base) & 1) == 0)) {
                longlong2 s0 = *(const longlong2*)(p + base);
                longlong2 s1 = *(const longlong2*)(p + base + 2);
                longlong2 d0 = *(const longlong2*)(p + E + base);
                longlong2 d1 = *(const longlong2*)(p + E + base + 2);
                ss[0] = (int)s0.x; ss[1] = (int)s0.y;
                ss[2] = (int)s1.x; ss[3] = (int)s1.y;
                dd[0] = (int)d0.x; dd[1] = (int)d0.y;
                dd[2] = (int)d1.x; dd[3] = (int)d1.y;
            } else {
                for (int j = 0; j < n; j++) {
                    ss[j] = (int)p[base + j];
                    dd[j] = (int)p[E + base + j];
                }
            }
        } else {
            const int* p = (const int*)edge;
            if (n == 4 && ((base & 3) == 0) && (((E + base) & 3) == 0)) {
                int4 s = *(const int4*)(p + base);
                int4 d = *(const int4*)(p + E + base);
                ss[0] = s.x; ss[1] = s.y; ss[2] = s.z; ss[3] = s.w;
                dd[0] = d.x; dd[1] = d.y; dd[2] = d.z; dd[3] = d.w;
            } else {
                for (int j = 0; j < n; j++) {
                    ss[j] = p[base + j];
                    dd[j] = p[E + base + j];
                }
            }
        }
        for (int j = 0; j < n; j++) {
            int pos = atomicAdd(&g_woff[dd[j]], 1);
            g_srcidx[pos] = ss[j];
        }
    } else {
        int nidx = i - E4;
        if (nidx < N) {
            int pos = atomicAdd(&g_woff[nidx], 1);
            g_srcidx[pos] = nidx;
        }
    }
}

// ---------------- tensor-core helpers ----------------
__device__ __forceinline__ uint32_t sptr(const void* p) {
    return (uint32_t)__cvta_generic_to_shared(p);
}
__device__ __forceinline__ void ldsm4(uint32_t* r, uint32_t a) {
    asm volatile("ldmatrix.sync.aligned.m8n8.x4.shared.b16 {%0,%1,%2,%3}, [%4];"
                 : "=r"(r[0]), "=r"(r[1]), "=r"(r[2]), "=r"(r[3]) : "r"(a));
}
__device__ __forceinline__ void ldsm4t(uint32_t* r, uint32_t a) {
    asm volatile("ldmatrix.sync.aligned.m8n8.x4.trans.shared.b16 {%0,%1,%2,%3}, [%4];"
                 : "=r"(r[0]), "=r"(r[1]), "=r"(r[2]), "=r"(r[3]) : "r"(a));
}
__device__ __forceinline__ void mma16816(float* c, const uint32_t* a, const uint32_t* b) {
    asm volatile("mma.sync.aligned.m16n8k16.row.col.f32.f16.f16.f32 "
                 "{%0,%1,%2,%3}, {%4,%5,%6,%7}, {%8,%9}, {%0,%1,%2,%3};"
                 : "+f"(c[0]), "+f"(c[1]), "+f"(c[2]), "+f"(c[3])
                 : "r"(a[0]), "r"(a[1]), "r"(a[2]), "r"(a[3]),
                   "r"(b[0]), "r"(b[1]));
}

// ---------------- GEMM layer 0: 64-row tiles, 3 terms, 2 CTAs/SM -----------
// 8 warps: warp_m = wid&1 (32 rows), warp_n = wid>>1 (32 cols = one head).
__global__ void __launch_bounds__(256)
gemm_tc64(int M, const float* __restrict__ asv, const float* __restrict__ adv) {
    extern __shared__ __half smem[];
    __half* sAhi = smem;
    __half* sAlo = smem + A64_T;
    __half* sWhi = smem + 2 * A64_T;
    __half* sWlo = sWhi + TILE_HALVES;

    const int tid = threadIdx.x;
    const int wid = tid >> 5;
    const int lane = tid & 31;
    const int warp_m = wid & 1;
    const int warp_n = wid >> 1;           // head index
    const int bm = blockIdx.x * 64;

    const uint4* wh = (const uint4*)g_Whi[0];
    const uint4* wl = (const uint4*)g_Wlo[0];
#pragma unroll
    for (int it = 0; it < 8; it++) {
        int flat = tid + it * 256;
        int row = flat >> 4, q = flat & 15;
        *(uint4*)(sWhi + row * SROW + q * 8) = wh[flat];
        *(uint4*)(sWlo + row * SROW + q * 8) = wl[flat];
    }
#pragma unroll
    for (int it = 0; it < 4; it++) {
        int flat = tid + it * 256;          // 1024 uint4
        int row = flat >> 4, q = flat & 15;
        int grow = bm + row;
        uint4 uh = make_uint4(0u, 0u, 0u, 0u);
        uint4 ul = make_uint4(0u, 0u, 0u, 0u);
        if (grow < M) {
            uh = ((const uint4*)g_xhi)[grow * 16 + q];
            ul = ((const uint4*)g_xlo)[grow * 16 + q];
        }
        *(uint4*)(sAhi + row * SROW + q * 8) = uh;
        *(uint4*)(sAlo + row * SROW + q * 8) = ul;
    }
    __syncthreads();

    float acc[2][4][4];
#pragma unroll
    for (int mt = 0; mt < 2; mt++)
#pragma unroll
        for (int nt = 0; nt < 4; nt++)
#pragma unroll
            for (int v = 0; v < 4; v++) acc[mt][nt][v] = 0.f;

    uint32_t aHiAddr[2], aLoAddr[2];
#pragma unroll
    for (int mt = 0; mt < 2; mt++) {
        int r = warp_m * 32 + mt * 16 + (lane & 15);
        int c = (lane >> 4) * 8;
        aHiAddr[mt] = sptr(sAhi + r * SROW + c);
        aLoAddr[mt] = sptr(sAlo + r * SROW + c);
    }
    uint32_t wHiAddr[2], wLoAddr[2];
#pragma unroll
    for (int p = 0; p < 2; p++) {
        int kr = (lane & 15);
        int c = warp_n * 32 + p * 16 + (lane >> 4) * 8;
        wHiAddr[p] = sptr(sWhi + kr * SROW + c);
        wLoAddr[p] = sptr(sWlo + kr * SROW + c);
    }

#pragma unroll
    for (int ks = 0; ks < 8; ks++) {
        uint32_t a_hi[2][4], a_lo[2][4];
#pragma unroll
        for (int mt = 0; mt < 2; mt++) {
            ldsm4(a_hi[mt], aHiAddr[mt] + ks * 32);
            ldsm4(a_lo[mt], aLoAddr[mt] + ks * 32);
        }
#pragma unroll
        for (int p = 0; p < 2; p++) {
            uint32_t bh[4], bl[4];
            ldsm4t(bh, wHiAddr[p] + ks * 16 * (SROW * 2));
            ldsm4t(bl, wLoAddr[p] + ks * 16 * (SROW * 2));
#pragma unroll
            for (int mt = 0; mt < 2; mt++) {
                mma16816(acc[mt][2 * p], a_hi[mt], bh);
                mma16816(acc[mt][2 * p], a_hi[mt], bl);
                mma16816(acc[mt][2 * p], a_lo[mt], bh);
                mma16816(acc[mt][2 * p + 1], a_hi[mt], bh + 2);
                mma16816(acc[mt][2 * p + 1], a_hi[mt], bl + 2);
                mma16816(acc[mt][2 * p + 1], a_lo[mt], bh + 2);
            }
        }
    }

    // epilogue: warp covers one head (32 cols)
    float as_v[4][2], ad_v[4][2];
#pragma unroll
    for (int nt = 0; nt < 4; nt++) {
        int col = warp_n * 32 + nt * 8 + (lane & 3) * 2;
        as_v[nt][0] = asv[col];     as_v[nt][1] = asv[col + 1];
        ad_v[nt][0] = adv[col];     ad_v[nt][1] = adv[col + 1];
    }
#pragma unroll
    for (int mt = 0; mt < 2; mt++) {
#pragma unroll
        for (int half = 0; half < 2; half++) {
            int row = bm + warp_m * 32 + mt * 16 + half * 8 + (lane >> 2);
            float ps = 0.f, pd = 0.f;
#pragma unroll
            for (int nt = 0; nt < 4; nt++) {
                float d0 = acc[mt][nt][half * 2], d1 = acc[mt][nt][half * 2 + 1];
                ps += d0 * as_v[nt][0] + d1 * as_v[nt][1];
                pd += d0 * ad_v[nt][0] + d1 * ad_v[nt][1];
            }
#pragma unroll
            for (int off = 1; off <= 2; off <<= 1) {
                ps += __shfl_xor_sync(0xffffffffu, ps, off);
                pd += __shfl_xor_sync(0xffffffffu, pd, off);
            }
            if ((lane & 3) == 0 && row < M) {
                g_asrc[row * 4 + warp_n] = ps;
                g_adst[row * 4 + warp_n] = pd;
            }
            if (row < M) {
#pragma unroll
                for (int nt = 0; nt < 4; nt++) {
                    int col = warp_n * 32 + nt * 8 + (lane & 3) * 2;
                    g_Hh[row * 64 + (col >> 1)] =
                        __floats2half2_rn(acc[mt][nt][half * 2],
                                          acc[mt][nt][half * 2 + 1]);
                }
            }
        }
    }
}

// ---------------- GEMM layers 1/2: 128x128 CTA, fp16 A, 2 terms ------------
__global__ void __launch_bounds__(256)
gemm_tc(int abuf, int widx, int M,
        const float* __restrict__ asv, const float* __restrict__ adv) {
    extern __shared__ __half smem[];
    __half* sAhi = smem;
    __half* sWhi = smem + TILE_HALVES;
    __half* sWlo = smem + 2 * TILE_HALVES;

    const __half2* Ahi_g = g_Hio[abuf];

    const int tid = threadIdx.x;
    const int wid = tid >> 5;
    const int lane = tid & 31;
    const int warp_m = wid & 3;
    const int warp_n = wid >> 2;
    const int bm = blockIdx.x * 128;

    const uint4* wh = (const uint4*)g_Whi[widx];
    const uint4* wl = (const uint4*)g_Wlo[widx];
#pragma unroll
    for (int it = 0; it < 8; it++) {
        int flat = tid + it * 256;
        int row = flat >> 4, q = flat & 15;
        *(uint4*)(sWhi + row * SROW + q * 8) = wh[flat];
        *(uint4*)(sWlo + row * SROW + q * 8) = wl[flat];
    }
#pragma unroll
    for (int it = 0; it < 8; it++) {
        int flat = tid + it * 256;
        int row = flat >> 4, q = flat & 15;
        int grow = bm + row;
        uint4 u = make_uint4(0u, 0u, 0u, 0u);
        if (grow < M) u = ((const uint4*)Ahi_g)[grow * 16 + q];
        *(uint4*)(sAhi + row * SROW + q * 8) = u;
    }
    __syncthreads();

    float acc[2][8][4];
#pragma unroll
    for (int mt = 0; mt < 2; mt++)
#pragma unroll
        for (int nt = 0; nt < 8; nt++)
#pragma unroll
            for (int v = 0; v < 4; v++) acc[mt][nt][v] = 0.f;

    uint32_t aHiAddr[2];
#pragma unroll
    for (int mt = 0; mt < 2; mt++) {
        int r = warp_m * 32 + mt * 16 + (lane & 15);
        int c = (lane >> 4) * 8;
        aHiAddr[mt] = sptr(sAhi + r * SROW + c);
    }
    uint32_t wHiAddr[4], wLoAddr[4];
#pragma unroll
    for (int p = 0; p < 4; p++) {
        int kr = (lane & 15);
        int c = warp_n * 64 + p * 16 + (lane >> 4) * 8;
        wHiAddr[p] = sptr(sWhi + kr * SROW + c);
        wLoAddr[p] = sptr(sWlo + kr * SROW + c);
    }

#pragma unroll
    for (int ks = 0; ks < 8; ks++) {
        uint32_t a_hi[2][4];
#pragma unroll
        for (int mt = 0; mt < 2; mt++)
            ldsm4(a_hi[mt], aHiAddr[mt] + ks * 32);
#pragma unroll
        for (int p = 0; p < 4; p++) {
            uint32_t bh[4], bl[4];
            ldsm4t(bh, wHiAddr[p] + ks * 16 * (SROW * 2));
            ldsm4t(bl, wLoAddr[p] + ks * 16 * (SROW * 2));
#pragma unroll
            for (int mt = 0; mt < 2; mt++) {
                mma16816(acc[mt][2 * p], a_hi[mt], bh);
                mma16816(acc[mt][2 * p], a_hi[mt], bl);
                mma16816(acc[mt][2 * p + 1], a_hi[mt], bh + 2);
                mma16816(acc[mt][2 * p + 1], a_hi[mt], bl + 2);
            }
        }
    }

    float as_v[8][2], ad_v[8][2];
#pragma unroll
    for (int nt = 0; nt < 8; nt++) {
        int col = warp_n * 64 + nt * 8 + (lane & 3) * 2;
        as_v[nt][0] = asv[col];     as_v[nt][1] = asv[col + 1];
        ad_v[nt][0] = adv[col];     ad_v[nt][1] = adv[col + 1];
    }
#pragma unroll
    for (int mt = 0; mt < 2; mt++) {
#pragma unroll
        for (int half = 0; half < 2; half++) {
            int row = bm + warp_m * 32 + mt * 16 + half * 8 + (lane >> 2);
            float psA = 0.f, pdA = 0.f, psB = 0.f, pdB = 0.f;
#pragma unroll
            for (int nt = 0; nt < 4; nt++) {
                float d0 = acc[mt][nt][half * 2], d1 = acc[mt][nt][half * 2 + 1];
                psA += d0 * as_v[nt][0] + d1 * as_v[nt][1];
                pdA += d0 * ad_v[nt][0] + d1 * ad_v[nt][1];
            }
#pragma unroll
            for (int nt = 4; nt < 8; nt++) {
                float d0 = acc[mt][nt][half * 2], d1 = acc[mt][nt][half * 2 + 1];
                psB += d0 * as_v[nt][0] + d1 * as_v[nt][1];
                pdB += d0 * ad_v[nt][0] + d1 * ad_v[nt][1];
            }
#pragma unroll
            for (int off = 1; off <= 2; off <<= 1) {
                psA += __shfl_xor_sync(0xffffffffu, psA, off);
                pdA += __shfl_xor_sync(0xffffffffu, pdA, off);
                psB += __shfl_xor_sync(0xffffffffu, psB, off);
                pdB += __shfl_xor_sync(0xffffffffu, pdB, off);
            }
            if ((lane & 3) == 0 && row < M) {
                int h0 = warp_n * 2;
                g_asrc[row * 4 + h0]     = psA;
                g_asrc[row * 4 + h0 + 1] = psB;
                g_adst[row * 4 + h0]     = pdA;
                g_adst[row * 4 + h0 + 1] = pdB;
            }
            if (row < M) {
#pragma unroll
                for (int nt = 0; nt < 8; nt++) {
                    int col = warp_n * 64 + nt * 8 + (lane & 3) * 2;
                    g_Hh[row * 64 + (col >> 1)] =
                        __floats2half2_rn(acc[mt][nt][half * 2],
                                          acc[mt][nt][half * 2 + 1]);
                }
            }
        }
    }
}

// ------- agg: smem-broadcast two-phase; phase2 = 2 edges/iter, LDG.128 -----
__global__ void __launch_bounds__(256)
agg_kernel(const float* __restrict__ bias, int outbuf, int Nn) {
    __shared__ int   sh_s[8][32];
    __shared__ float sh_p[8][32][4];
    int w = threadIdx.x >> 5;
    int gwarp = (blockIdx.x * blockDim.x + threadIdx.x) >> 5;
    int lane = threadIdx.x & 31;
    if (gwarp >= Nn) return;
    const float4* asrc4 = (const float4*)g_asrc;
    __half2* Out = g_Hio[outbuf];
    int d = gwarp;
    int j0 = g_rowptr[d];
    int j1 = g_rowptr[d + 1];
    int sub = lane & 15;
    int eh  = lane >> 4;
    int head = sub >> 2;

    float4 adv = ((const float4*)g_adst)[d];

    float acc[8];
#pragma unroll
    for (int i = 0; i < 8; i++) acc[i] = 0.f;
    float psum[NHEAD] = {0.f, 0.f, 0.f, 0.f};

    for (int base = j0; base < j1; base += 32) {
        int j = base + lane;
        if (j < j1) {
            int s = g_srcidx[j];
            float4 av = asrc4[s];
            float e0 = av.x + adv.x; e0 = (e0 > 0.f) ? e0 : 0.2f * e0;
            float e1 = av.y + adv.y; e1 = (e1 > 0.f) ? e1 : 0.2f * e1;
            float e2 = av.z + adv.z; e2 = (e2 > 0.f) ? e2 : 0.2f * e2;
            float e3 = av.w + adv.w; e3 = (e3 > 0.f) ? e3 : 0.2f * e3;
            float p0 = __expf(e0), p1 = __expf(e1);
            float p2 = __expf(e2), p3 = __expf(e3);
            psum[0] += p0; psum[1] += p1; psum[2] += p2; psum[3] += p3;
            sh_s[w][lane] = s;
            *(float4*)&sh_p[w][lane][0] = make_float4(p0, p1, p2, p3);
        }
        __syncwarp();
        int cnt = min(32, j1 - base);
#pragma unroll 4
        for (int k = 0; k < cnt; k += 2) {
            int kk = k + eh;
            float pk = 0.f;
            int sk = sh_s[w][k];
            if (kk < cnt) { sk = sh_s[w][kk]; pk = sh_p[w][kk][head]; }
            uint4 u = __ldg(&((const uint4*)(g_Hh + sk * 64))[sub]);
            float2 f0 = __half22float2(*(const __half2*)&u.x);
            float2 f1 = __half22float2(*(const __half2*)&u.y);
            float2 f2 = __half22float2(*(const __half2*)&u.z);
            float2 f3 = __half22float2(*(const __half2*)&u.w);
            acc[0] += pk * f0.x; acc[1] += pk * f0.y;
            acc[2] += pk * f1.x; acc[3] += pk * f1.y;
            acc[4] += pk * f2.x; acc[5] += pk * f2.y;
            acc[6] += pk * f3.x; acc[7] += pk * f3.y;
        }
        __syncwarp();
    }
#pragma unroll
    for (int i = 0; i < 8; i++)
        acc[i] += __shfl_xor_sync(0xffffffffu, acc[i], 16);
#pragma unroll
    for (int h = 0; h < NHEAD; h++)
        for (int off = 16; off > 0; off >>= 1)
            psum[h] += __shfl_xor_sync(0xffffffffu, psum[h], off);

    if (eh == 0) {
        float pd = (head == 0) ? psum[0] : (head == 1) ? psum[1]
                 : (head == 2) ? psum[2] : psum[3];
        float rinv = 1.0f / pd;
        float4 b0 = *(const float4*)(bias + sub * 8);
        float4 b1 = *(const float4*)(bias + sub * 8 + 4);
        __half2 h0 = __floats2half2_rn(fmaxf(acc[0] * rinv + b0.x, 0.f),
                                       fmaxf(acc[1] * rinv + b0.y, 0.f));
        __half2 h1 = __floats2half2_rn(fmaxf(acc[2] * rinv + b0.z, 0.f),
                                       fmaxf(acc[3] * rinv + b0.w, 0.f));
        __half2 h2 = __floats2half2_rn(fmaxf(acc[4] * rinv + b1.x, 0.f),
                                       fmaxf(acc[5] * rinv + b1.y, 0.f));
        __half2 h3 = __floats2half2_rn(fmaxf(acc[6] * rinv + b1.z, 0.f),
                                       fmaxf(acc[7] * rinv + b1.w, 0.f));
        uint4 st;
        st.x = *(const uint32_t*)&h0;
        st.y = *(const uint32_t*)&h1;
        st.z = *(const uint32_t*)&h2;
        st.w = *(const uint32_t*)&h3;
        ((uint4*)(Out + d * 64))[sub] = st;
    }
}

// ---------------- fused pool (block/graph, batch sorted) + MLP --------------
__device__ __forceinline__ int lower_bound_dev(const int* a, int n, int v) {
    int lo = 0, hi = n;
    while (lo < hi) { int m = (lo + hi) >> 1; if (a[m] < v) lo = m + 1; else hi = m; }
    return lo;
}

__global__ void pool_mlp_kernel(int inbuf, int Nn,
                                const float* __restrict__ Wlin,
                                const float* __restrict__ blin,
                                const float* __restrict__ Wout,
                                const float* __restrict__ bout,
                                float* __restrict__ out) {
    __shared__ float pooled[HCDIM];
    __shared__ float z[LINDIM];
    __shared__ int srange[2];
    int g = blockIdx.x;
    int t = threadIdx.x;
    if (t < 2) srange[t] = lower_bound_dev(g_bnode, Nn, g + t);
    __syncthreads();
    int s0 = srange[0], s1 = srange[1];
    if (t < HCDIM) {
        const __half* Hf = (const __half*)g_Hio[inbuf];
        float m = 0.f;
        for (int n = s0; n < s1; n++)
            m = fmaxf(m, __half2float(Hf[n * HCDIM + t]));
        pooled[t] = m;
    }
    __syncthreads();
    {
        float acc = blin[t];
#pragma unroll 8
        for (int k = 0; k < HCDIM; k++)
            acc += pooled[k] * Wlin[k * LINDIM + t];
        z[t] = acc;
    }
    __syncthreads();
    if (t < OUTDIM) {
        float acc = bout[t];
#pragma unroll 8
        for (int k = 0; k < LINDIM; k++)
            acc += z[k] * Wout[k * OUTDIM + t];
        out[g * OUTDIM + t] = acc;
    }
}

// ---------------- launcher ----------------
extern "C" void kernel_launch(void* const* d_in, const int* in_sizes, int n_in,
                              void* d_out, int out_size) {
    const float* x     = (const float*)d_in[0];
    const void*  edge  = d_in[1];
    const void*  batch = d_in[2];
    const float* W0 = (const float*)d_in[3];
    const float* as0 = (const float*)d_in[4];
    const float* ad0 = (const float*)d_in[5];
    const float* b0 = (const float*)d_in[6];
    const float* W1 = (const float*)d_in[7];
    const float* as1 = (const float*)d_in[8];
    const float* ad1 = (const float*)d_in[9];
    const float* b1 = (const float*)d_in[10];
    const float* W2 = (const float*)d_in[11];
    const float* as2 = (const float*)d_in[12];
    const float* ad2 = (const float*)d_in[13];
    const float* b2 = (const float*)d_in[14];
    const float* Wlin = (const float*)d_in[15];
    const float* blin = (const float*)d_in[16];
    const float* Wout = (const float*)d_in[17];
    const float* bout = (const float*)d_in[18];
    float* out = (float*)d_out;

    int N = in_sizes[0] / HCDIM;
    int E = in_sizes[1] / 2;

    cudaFuncSetAttribute(gemm_tc64,
                         cudaFuncAttributeMaxDynamicSharedMemorySize, SMEM_L0);
    cudaFuncSetAttribute(gemm_tc,
                         cudaFuncAttributeMaxDynamicSharedMemorySize, SMEM_L12);

    // side stream + events for the independent CSR chain (created once;
    // host-side resources only — no device memory)
    static cudaStream_t s2 = nullptr;
    static cudaEvent_t evFork = nullptr, evJoin = nullptr;
    if (s2 == nullptr) {
        cudaStreamCreateWithFlags(&s2, cudaStreamNonBlocking);
        cudaEventCreateWithFlags(&evFork, cudaEventDisableTiming);
        cudaEventCreateWithFlags(&evJoin, cudaEventDisableTiming);
    }

    int MB64 = (N + 63) / 64;
    int MB = (N + 127) / 128;
    int aggBlocks = (N * 32 + 255) / 256;
    int NB = (N + 1023) / 1024;
    int E4 = (E + 3) / 4;

    // fork: CSR chain on s2, GEMM prep chain on legacy stream
    cudaEventRecord(evFork, 0);
    cudaStreamWaitEvent(s2, evFork, 0);
    init_node<<<(N + 255) / 256, 256, 0, s2>>>(batch, N);
    hist_kernel<<<(E4 + 255) / 256, 256, 0, s2>>>(edge, E, N);
    scan_block<<<NB, 1024, 0, s2>>>(N);
    scan_add2<<<(N + 255) / 256, 256, 0, s2>>>(N, E + N);
    scatter_kernel<<<(E4 + N + 255) / 256, 256, 0, s2>>>(edge, E, N);
    cudaEventRecord(evJoin, s2);

    prep_all<<<(N * 32 + 255) / 256, 256>>>(x, W0, W1, W2, N);
    gemm_tc64<<<MB64, 256, SMEM_L0>>>(N, as0, ad0);

    // join: agg needs both CSR + gemm0
    cudaStreamWaitEvent(0, evJoin, 0);

    agg_kernel<<<aggBlocks, 256>>>(b0, 0, N);
    gemm_tc<<<MB, 256, SMEM_L12>>>(0, 1, N, as1, ad1);
    agg_kernel<<<aggBlocks, 256>>>(b1, 1, N);
    gemm_tc<<<MB, 256, SMEM_L12>>>(1, 2, N, as2, ad2);
    agg_kernel<<<aggBlocks, 256>>>(b2, 0, N);

    pool_mlp_kernel<<<GN, LINDIM>>>(0, N, Wlin, blin, Wout, bout, out);
}

// round 15
// speedup vs baseline: 1.0321x; 1.0321x over previous
#include <cuda_runtime.h>
#include <cuda_fp16.h>
#include <stdint.h>
#include <math.h>

#define MAXN 50016
#define MAXE 800000
#define MAXET (MAXE + MAXN)
#define HCDIM 128
#define NHEAD 4
#define GN 64
#define LINDIM 256
#define OUTDIM 10

#define SROW 136                       // smem row stride in halves (128 + 8 pad)
#define TILE_HALVES (128 * SROW)       // 17408 halves = 34816 B
#define SMEM_G (3 * TILE_HALVES * 2)   // Ahi + Whi + Wlo = 104448 B

// ---------------- device scratch ----------------
__device__ int   g_counts[MAXN];
__device__ int   g_rowptr[MAXN + 1];
__device__ int   g_woff[MAXN];
__device__ int   g_srcidx[MAXET];
__device__ int   g_bnode[MAXN];
__device__ __align__(16) float g_asrc[MAXN * NHEAD];
__device__ __align__(16) float g_adst[MAXN * NHEAD];
__device__ __half2 g_Hh[MAXN * (HCDIM / 2)];        // GEMM out (gather src)
__device__ __half2 g_Hio[2][MAXN * (HCDIM / 2)];    // layer io
__device__ __half2 g_xhi[MAXN * (HCDIM / 2)];       // fp16(x)
__device__ __align__(16) __half g_Whi[3][HCDIM * HCDIM];
__device__ __align__(16) __half g_Wlo[3][HCDIM * HCDIM];
__device__ int   g_bsums[128];

// ---------------- dtype detection helpers ----------------
__device__ __forceinline__ bool edge_is64(const void* edge, long long N) {
    const long long* p = (const long long*)edge;
    int lane = threadIdx.x & 31;
    long long v0 = p[lane];
    long long v1 = p[lane + 32];
    bool bad = (v0 < 0) | (v0 >= N) | (v1 < 0) | (v1 >= N);
    return __all_sync(0xffffffffu, !bad);
}
__device__ __forceinline__ bool batch_is64(const void* batch, int N) {
    const long long* p = (const long long*)batch;
    int lane = threadIdx.x & 31;
    int idx = N / 2 - 1 - lane;
    long long v = (idx >= 0) ? p[idx] : 0;
    bool bad = (v < 0) | (v >= 64);
    return __all_sync(0xffffffffu, !bad);
}

// ---------------- fused prep: W split + x fp16 + node init ----------------
__global__ void prep_all(const float* __restrict__ x,
                         const float* __restrict__ w0,
                         const float* __restrict__ w1,
                         const float* __restrict__ w2,
                         const void* batch, int N) {
    bool b64 = batch_is64(batch, N);
    int idx = blockIdx.x * blockDim.x + threadIdx.x;

    if (idx < 3 * HCDIM * HCDIM) {
        int m = idx >> 14;
        int r = idx & 16383;
        const float* w = (m == 0) ? w0 : (m == 1) ? w1 : w2;
        float v = w[r];
        __half hi = __float2half_rn(v);
        g_Whi[m][r] = hi;
        g_Wlo[m][r] = __float2half_rn(v - __half2float(hi));
    }
    if (idx < N) {
        g_counts[idx] = 1;
        g_bnode[idx] = b64 ? (int)((const long long*)batch)[idx]
                           : ((const int*)batch)[idx];
    }
    if (idx < N * 32) {
        float4 v = ((const float4*)x)[idx];
        __half2 hiA = __floats2half2_rn(v.x, v.y);
        __half2 hiB = __floats2half2_rn(v.z, v.w);
        uint2 sh;
        sh.x = *(const uint32_t*)&hiA;  sh.y = *(const uint32_t*)&hiB;
        ((uint2*)g_xhi)[idx] = sh;
    }
}

// histogram over dst, 4 edges/thread, vector loads
__global__ void hist_kernel(const void* edge, int E, int N) {
    bool e64 = edge_is64(edge, (long long)N);
    int base = (blockIdx.x * blockDim.x + threadIdx.x) * 4;
    if (base >= E) return;
    int n = min(4, E - base);
    int dd[4];
    if (e64) {
        const long long* p = (const long long*)edge + E;
        if (n == 4 && (((E + base) & 1) == 0)) {
            longlong2 v0 = *(const longlong2*)(p + base);
            longlong2 v1 = *(const longlong2*)(p + base + 2);
            dd[0] = (int)v0.x; dd[1] = (int)v0.y;
            dd[2] = (int)v1.x; dd[3] = (int)v1.y;
        } else {
            for (int j = 0; j < n; j++) dd[j] = (int)p[base + j];
        }
    } else {
        const int* p = (const int*)edge + E;
        if (n == 4 && (((E + base) & 3) == 0)) {
            int4 v = *(const int4*)(p + base);
            dd[0] = v.x; dd[1] = v.y; dd[2] = v.z; dd[3] = v.w;
        } else {
            for (int j = 0; j < n; j++) dd[j] = p[base + j];
        }
    }
    for (int j = 0; j < n; j++) atomicAdd(&g_counts[dd[j]], 1);
}

__global__ void scan_block(int N) {
    __shared__ int sh[1024];
    int i = blockIdx.x * 1024 + threadIdx.x;
    int v = (i < N) ? g_counts[i] : 0;
    sh[threadIdx.x] = v;
    __syncthreads();
    for (int off = 1; off < 1024; off <<= 1) {
        int x = 0;
        if (threadIdx.x >= off) x = sh[threadIdx.x - off];
        __syncthreads();
        if (threadIdx.x >= off) sh[threadIdx.x] += x;
        __syncthreads();
    }
    if (i < N) g_rowptr[i] = sh[threadIdx.x] - v;
    if (threadIdx.x == 1023) g_bsums[blockIdx.x] = sh[1023];
}

// block offset via warp-parallel reduce (was: serial dependent-load loop)
__global__ void scan_add2(int N, int total) {
    __shared__ int off0;
    int chunk = (blockIdx.x * blockDim.x) >> 10;
    if (threadIdx.x < 32) {
        int acc = 0;
        for (int b = (int)threadIdx.x; b < chunk; b += 32) acc += g_bsums[b];
        for (int off = 16; off > 0; off >>= 1)
            acc += __shfl_xor_sync(0xffffffffu, acc, off);
        if (threadIdx.x == 0) off0 = acc;
    }
    __syncthreads();
    int i = blockIdx.x * blockDim.x + threadIdx.x;
    if (i < N) {
        int r = g_rowptr[i] + off0;
        g_rowptr[i] = r;
        g_woff[i] = r;
    }
    if (i == 0) g_rowptr[N] = total;
}

// scatter: 4 edges/thread with vector loads, then self-loops
__global__ void scatter_kernel(const void* edge, int E, int N) {
    bool e64 = edge_is64(edge, (long long)N);
    int E4 = (E + 3) >> 2;
    int i = blockIdx.x * blockDim.x + threadIdx.x;
    if (i < E4) {
        int base = i * 4;
        int n = min(4, E - base);
        int ss[4], dd[4];
        if (e64) {
            const long long* p = (const long long*)edge;
            if (n == 4 && ((base & 1) == 0) && (((E + base) & 1) == 0)) {
                longlong2 s0 = *(const longlong2*)(p + base);
                longlong2 s1 = *(const longlong2*)(p + base + 2);
                longlong2 d0 = *(const longlong2*)(p + E + base);
                longlong2 d1 = *(const longlong2*)(p + E + base + 2);
                ss[0] = (int)s0.x; ss[1] = (int)s0.y;
                ss[2] = (int)s1.x; ss[3] = (int)s1.y;
                dd[0] = (int)d0.x; dd[1] = (int)d0.y;
                dd[2] = (int)d1.x; dd[3] = (int)d1.y;
            } else {
                for (int j = 0; j < n; j++) {
                    ss[j] = (int)p[base + j];
                    dd[j] = (int)p[E + base + j];
                }
            }
        } else {
            const int* p = (const int*)edge;
            if (n == 4 && ((base & 3) == 0) && (((E + base) & 3) == 0)) {
                int4 s = *(const int4*)(p + base);
                int4 d = *(const int4*)(p + E + base);
                ss[0] = s.x; ss[1] = s.y; ss[2] = s.z; ss[3] = s.w;
                dd[0] = d.x; dd[1] = d.y; dd[2] = d.z; dd[3] = d.w;
            } else {
                for (int j = 0; j < n; j++) {
                    ss[j] = p[base + j];
                    dd[j] = p[E + base + j];
                }
            }
        }
        for (int j = 0; j < n; j++) {
            int pos = atomicAdd(&g_woff[dd[j]], 1);
            g_srcidx[pos] = ss[j];
        }
    } else {
        int nidx = i - E4;
        if (nidx < N) {
            int pos = atomicAdd(&g_woff[nidx], 1);
            g_srcidx[pos] = nidx;
        }
    }
}

// ---------------- tensor-core helpers ----------------
__device__ __forceinline__ uint32_t sptr(const void* p) {
    return (uint32_t)__cvta_generic_to_shared(p);
}
__device__ __forceinline__ void ldsm4(uint32_t* r, uint32_t a) {
    asm volatile("ldmatrix.sync.aligned.m8n8.x4.shared.b16 {%0,%1,%2,%3}, [%4];"
                 : "=r"(r[0]), "=r"(r[1]), "=r"(r[2]), "=r"(r[3]) : "r"(a));
}
__device__ __forceinline__ void ldsm4t(uint32_t* r, uint32_t a) {
    asm volatile("ldmatrix.sync.aligned.m8n8.x4.trans.shared.b16 {%0,%1,%2,%3}, [%4];"
                 : "=r"(r[0]), "=r"(r[1]), "=r"(r[2]), "=r"(r[3]) : "r"(a));
}
__device__ __forceinline__ void mma16816(float* c, const uint32_t* a, const uint32_t* b) {
    asm volatile("mma.sync.aligned.m16n8k16.row.col.f32.f16.f16.f32 "
                 "{%0,%1,%2,%3}, {%4,%5,%6,%7}, {%8,%9}, {%0,%1,%2,%3};"
                 : "+f"(c[0]), "+f"(c[1]), "+f"(c[2]), "+f"(c[3])
                 : "r"(a[0]), "r"(a[1]), "r"(a[2]), "r"(a[3]),
                   "r"(b[0]), "r"(b[1]));
}

// ---------------- GEMM (all 3 layers): 128x128 CTA, fp16 A, 2 terms --------
// abuf: -1 -> g_xhi (layer 0), else g_Hio[abuf].
__global__ void __launch_bounds__(256)
gemm_tc(int abuf, int widx, int M,
        const float* __restrict__ asv, const float* __restrict__ adv) {
    extern __shared__ __half smem[];
    __half* sAhi = smem;
    __half* sWhi = smem + TILE_HALVES;
    __half* sWlo = smem + 2 * TILE_HALVES;

    const __half2* Ahi_g = (abuf < 0) ? g_xhi : g_Hio[abuf];

    const int tid = threadIdx.x;
    const int wid = tid >> 5;
    const int lane = tid & 31;
    const int warp_m = wid & 3;
    const int warp_n = wid >> 2;
    const int bm = blockIdx.x * 128;

    const uint4* wh = (const uint4*)g_Whi[widx];
    const uint4* wl = (const uint4*)g_Wlo[widx];
#pragma unroll
    for (int it = 0; it < 8; it++) {
        int flat = tid + it * 256;
        int row = flat >> 4, q = flat & 15;
        *(uint4*)(sWhi + row * SROW + q * 8) = wh[flat];
        *(uint4*)(sWlo + row * SROW + q * 8) = wl[flat];
    }
#pragma unroll
    for (int it = 0; it < 8; it++) {
        int flat = tid + it * 256;
        int row = flat >> 4, q = flat & 15;
        int grow = bm + row;
        uint4 u = make_uint4(0u, 0u, 0u, 0u);
        if (grow < M) u = ((const uint4*)Ahi_g)[grow * 16 + q];
        *(uint4*)(sAhi + row * SROW + q * 8) = u;
    }
    __syncthreads();

    float acc[2][8][4];
#pragma unroll
    for (int mt = 0; mt < 2; mt++)
#pragma unroll
        for (int nt = 0; nt < 8; nt++)
#pragma unroll
            for (int v = 0; v < 4; v++) acc[mt][nt][v] = 0.f;

    uint32_t aHiAddr[2];
#pragma unroll
    for (int mt = 0; mt < 2; mt++) {
        int r = warp_m * 32 + mt * 16 + (lane & 15);
        int c = (lane >> 4) * 8;
        aHiAddr[mt] = sptr(sAhi + r * SROW + c);
    }
    uint32_t wHiAddr[4], wLoAddr[4];
#pragma unroll
    for (int p = 0; p < 4; p++) {
        int kr = (lane & 15);
        int c = warp_n * 64 + p * 16 + (lane >> 4) * 8;
        wHiAddr[p] = sptr(sWhi + kr * SROW + c);
        wLoAddr[p] = sptr(sWlo + kr * SROW + c);
    }

#pragma unroll
    for (int ks = 0; ks < 8; ks++) {
        uint32_t a_hi[2][4];
#pragma unroll
        for (int mt = 0; mt < 2; mt++)
            ldsm4(a_hi[mt], aHiAddr[mt] + ks * 32);
#pragma unroll
        for (int p = 0; p < 4; p++) {
            uint32_t bh[4], bl[4];
            ldsm4t(bh, wHiAddr[p] + ks * 16 * (SROW * 2));
            ldsm4t(bl, wLoAddr[p] + ks * 16 * (SROW * 2));
#pragma unroll
            for (int mt = 0; mt < 2; mt++) {
                mma16816(acc[mt][2 * p], a_hi[mt], bh);
                mma16816(acc[mt][2 * p], a_hi[mt], bl);
                mma16816(acc[mt][2 * p + 1], a_hi[mt], bh + 2);
                mma16816(acc[mt][2 * p + 1], a_hi[mt], bl + 2);
            }
        }
    }

    // ---------- epilogue: fp16 Hh store + fused per-head alpha dots ----------
    float as_v[8][2], ad_v[8][2];
#pragma unroll
    for (int nt = 0; nt < 8; nt++) {
        int col = warp_n * 64 + nt * 8 + (lane & 3) * 2;
        as_v[nt][0] = asv[col];     as_v[nt][1] = asv[col + 1];
        ad_v[nt][0] = adv[col];     ad_v[nt][1] = adv[col + 1];
    }
#pragma unroll
    for (int mt = 0; mt < 2; mt++) {
#pragma unroll
        for (int half = 0; half < 2; half++) {
            int row = bm + warp_m * 32 + mt * 16 + half * 8 + (lane >> 2);
            float psA = 0.f, pdA = 0.f, psB = 0.f, pdB = 0.f;
#pragma unroll
            for (int nt = 0; nt < 4; nt++) {
                float d0 = acc[mt][nt][half * 2], d1 = acc[mt][nt][half * 2 + 1];
                psA += d0 * as_v[nt][0] + d1 * as_v[nt][1];
                pdA += d0 * ad_v[nt][0] + d1 * ad_v[nt][1];
            }
#pragma unroll
            for (int nt = 4; nt < 8; nt++) {
                float d0 = acc[mt][nt][half * 2], d1 = acc[mt][nt][half * 2 + 1];
                psB += d0 * as_v[nt][0] + d1 * as_v[nt][1];
                pdB += d0 * ad_v[nt][0] + d1 * ad_v[nt][1];
            }
#pragma unroll
            for (int off = 1; off <= 2; off <<= 1) {
                psA += __shfl_xor_sync(0xffffffffu, psA, off);
                pdA += __shfl_xor_sync(0xffffffffu, pdA, off);
                psB += __shfl_xor_sync(0xffffffffu, psB, off);
                pdB += __shfl_xor_sync(0xffffffffu, pdB, off);
            }
            if ((lane & 3) == 0 && row < M) {
                int h0 = warp_n * 2;
                g_asrc[row * 4 + h0]     = psA;
                g_asrc[row * 4 + h0 + 1] = psB;
                g_adst[row * 4 + h0]     = pdA;
                g_adst[row * 4 + h0 + 1] = pdB;
            }
            if (row < M) {
#pragma unroll
                for (int nt = 0; nt < 8; nt++) {
                    int col = warp_n * 64 + nt * 8 + (lane & 3) * 2;
                    g_Hh[row * 64 + (col >> 1)] =
                        __floats2half2_rn(acc[mt][nt][half * 2],
                                          acc[mt][nt][half * 2 + 1]);
                }
            }
        }
    }
}

// ------- agg: smem-broadcast two-phase; phase2 = 2 edges/iter, LDG.128 -----
__global__ void __launch_bounds__(256)
agg_kernel(const float* __restrict__ bias, int outbuf, int Nn) {
    __shared__ int   sh_s[8][32];
    __shared__ float sh_p[8][32][4];
    int w = threadIdx.x >> 5;
    int gwarp = (blockIdx.x * blockDim.x + threadIdx.x) >> 5;
    int lane = threadIdx.x & 31;
    if (gwarp >= Nn) return;
    const float4* asrc4 = (const float4*)g_asrc;
    __half2* Out = g_Hio[outbuf];
    int d = gwarp;
    int j0 = g_rowptr[d];
    int j1 = g_rowptr[d + 1];
    int sub = lane & 15;
    int eh  = lane >> 4;
    int head = sub >> 2;

    float4 adv = ((const float4*)g_adst)[d];

    float acc[8];
#pragma unroll
    for (int i = 0; i < 8; i++) acc[i] = 0.f;
    float psum[NHEAD] = {0.f, 0.f, 0.f, 0.f};

    for (int base = j0; base < j1; base += 32) {
        int j = base + lane;
        if (j < j1) {
            int s = g_srcidx[j];
            float4 av = asrc4[s];
            float e0 = av.x + adv.x; e0 = (e0 > 0.f) ? e0 : 0.2f * e0;
            float e1 = av.y + adv.y; e1 = (e1 > 0.f) ? e1 : 0.2f * e1;
            float e2 = av.z + adv.z; e2 = (e2 > 0.f) ? e2 : 0.2f * e2;
            float e3 = av.w + adv.w; e3 = (e3 > 0.f) ? e3 : 0.2f * e3;
            float p0 = __expf(e0), p1 = __expf(e1);
            float p2 = __expf(e2), p3 = __expf(e3);
            psum[0] += p0; psum[1] += p1; psum[2] += p2; psum[3] += p3;
            sh_s[w][lane] = s;
            *(float4*)&sh_p[w][lane][0] = make_float4(p0, p1, p2, p3);
        }
        __syncwarp();
        int cnt = min(32, j1 - base);
#pragma unroll 4
        for (int k = 0; k < cnt; k += 2) {
            int kk = k + eh;
            float pk = 0.f;
            int sk = sh_s[w][k];
            if (kk < cnt) { sk = sh_s[w][kk]; pk = sh_p[w][kk][head]; }
            uint4 u = __ldg(&((const uint4*)(g_Hh + sk * 64))[sub]);
            float2 f0 = __half22float2(*(const __half2*)&u.x);
            float2 f1 = __half22float2(*(const __half2*)&u.y);
            float2 f2 = __half22float2(*(const __half2*)&u.z);
            float2 f3 = __half22float2(*(const __half2*)&u.w);
            acc[0] += pk * f0.x; acc[1] += pk * f0.y;
            acc[2] += pk * f1.x; acc[3] += pk * f1.y;
            acc[4] += pk * f2.x; acc[5] += pk * f2.y;
            acc[6] += pk * f3.x; acc[7] += pk * f3.y;
        }
        __syncwarp();
    }
#pragma unroll
    for (int i = 0; i < 8; i++)
        acc[i] += __shfl_xor_sync(0xffffffffu, acc[i], 16);
#pragma unroll
    for (int h = 0; h < NHEAD; h++)
        for (int off = 16; off > 0; off >>= 1)
            psum[h] += __shfl_xor_sync(0xffffffffu, psum[h], off);

    if (eh == 0) {
        float pd = (head == 0) ? psum[0] : (head == 1) ? psum[1]
                 : (head == 2) ? psum[2] : psum[3];
        float rinv = 1.0f / pd;
        float4 b0 = *(const float4*)(bias + sub * 8);
        float4 b1 = *(const float4*)(bias + sub * 8 + 4);
        __half2 h0 = __floats2half2_rn(fmaxf(acc[0] * rinv + b0.x, 0.f),
                                       fmaxf(acc[1] * rinv + b0.y, 0.f));
        __half2 h1 = __floats2half2_rn(fmaxf(acc[2] * rinv + b0.z, 0.f),
                                       fmaxf(acc[3] * rinv + b0.w, 0.f));
        __half2 h2 = __floats2half2_rn(fmaxf(acc[4] * rinv + b1.x, 0.f),
                                       fmaxf(acc[5] * rinv + b1.y, 0.f));
        __half2 h3 = __floats2half2_rn(fmaxf(acc[6] * rinv + b1.z, 0.f),
                                       fmaxf(acc[7] * rinv + b1.w, 0.f));
        uint4 st;
        st.x = *(const uint32_t*)&h0;
        st.y = *(const uint32_t*)&h1;
        st.z = *(const uint32_t*)&h2;
        st.w = *(const uint32_t*)&h3;
        ((uint4*)(Out + d * 64))[sub] = st;
    }
}

// ---------------- fused pool (block/graph, batch sorted) + MLP --------------
__device__ __forceinline__ int lower_bound_dev(const int* a, int n, int v) {
    int lo = 0, hi = n;
    while (lo < hi) { int m = (lo + hi) >> 1; if (a[m] < v) lo = m + 1; else hi = m; }
    return lo;
}

__global__ void pool_mlp_kernel(int inbuf, int Nn,
                                const float* __restrict__ Wlin,
                                const float* __restrict__ blin,
                                const float* __restrict__ Wout,
                                const float* __restrict__ bout,
                                float* __restrict__ out) {
    __shared__ float pooled[HCDIM];
    __shared__ float z[LINDIM];
    __shared__ int srange[2];
    int g = blockIdx.x;
    int t = threadIdx.x;
    if (t < 2) srange[t] = lower_bound_dev(g_bnode, Nn, g + t);
    __syncthreads();
    int s0 = srange[0], s1 = srange[1];
    if (t < HCDIM) {
        const __half* Hf = (const __half*)g_Hio[inbuf];
        float m = 0.f;
        for (int n = s0; n < s1; n++)
            m = fmaxf(m, __half2float(Hf[n * HCDIM + t]));
        pooled[t] = m;
    }
    __syncthreads();
    {
        float acc = blin[t];
#pragma unroll 8
        for (int k = 0; k < HCDIM; k++)
            acc += pooled[k] * Wlin[k * LINDIM + t];
        z[t] = acc;
    }
    __syncthreads();
    if (t < OUTDIM) {
        float acc = bout[t];
#pragma unroll 8
        for (int k = 0; k < LINDIM; k++)
            acc += z[k] * Wout[k * OUTDIM + t];
        out[g * OUTDIM + t] = acc;
    }
}

// ---------------- launcher ----------------
extern "C" void kernel_launch(void* const* d_in, const int* in_sizes, int n_in,
                              void* d_out, int out_size) {
    const float* x     = (const float*)d_in[0];
    const void*  edge  = d_in[1];
    const void*  batch = d_in[2];
    const float* W0 = (const float*)d_in[3];
    const float* as0 = (const float*)d_in[4];
    const float* ad0 = (const float*)d_in[5];
    const float* b0 = (const float*)d_in[6];
    const float* W1 = (const float*)d_in[7];
    const float* as1 = (const float*)d_in[8];
    const float* ad1 = (const float*)d_in[9];
    const float* b1 = (const float*)d_in[10];
    const float* W2 = (const float*)d_in[11];
    const float* as2 = (const float*)d_in[12];
    const float* ad2 = (const float*)d_in[13];
    const float* b2 = (const float*)d_in[14];
    const float* Wlin = (const float*)d_in[15];
    const float* blin = (const float*)d_in[16];
    const float* Wout = (const float*)d_in[17];
    const float* bout = (const float*)d_in[18];
    float* out = (float*)d_out;

    int N = in_sizes[0] / HCDIM;
    int E = in_sizes[1] / 2;

    cudaFuncSetAttribute(gemm_tc,
                         cudaFuncAttributeMaxDynamicSharedMemorySize, SMEM_G);

    int MB = (N + 127) / 128;
    int aggBlocks = (N * 32 + 255) / 256;
    int NB = (N + 1023) / 1024;
    int E4 = (E + 3) / 4;

    prep_all<<<(N * 32 + 255) / 256, 256>>>(x, W0, W1, W2, batch, N);
    hist_kernel<<<(E4 + 255) / 256, 256>>>(edge, E, N);
    scan_block<<<NB, 1024>>>(N);
    // 4th launch -> ncu profile slot: layer-0 GEMM (independent of CSR)
    gemm_tc<<<MB, 256, SMEM_G>>>(-1, 0, N, as0, ad0);
    scan_add2<<<(N + 255) / 256, 256>>>(N, E + N);
    scatter_kernel<<<(E4 + N + 255) / 256, 256>>>(edge, E, N);

    agg_kernel<<<aggBlocks, 256>>>(b0, 0, N);
    gemm_tc<<<MB, 256, SMEM_G>>>(0, 1, N, as1, ad1);
    agg_kernel<<<aggBlocks, 256>>>(b1, 1, N);
    gemm_tc<<<MB, 256, SMEM_G>>>(1, 2, N, as2, ad2);
    agg_kernel<<<aggBlocks, 256>>>(b2, 0, N);

    pool_mlp_kernel<<<GN, LINDIM>>>(0, N, Wlin, blin, Wout, bout, out);
}

// round 16
// speedup vs baseline: 1.0815x; 1.0479x over previous
#include <cuda_runtime.h>
#include <cuda_fp16.h>
#include <stdint.h>
#include <math.h>

#define MAXN 50016
#define MAXE 800000
#define MAXET (MAXE + MAXN)
#define HCDIM 128
#define NHEAD 4
#define GN 64
#define LINDIM 256
#define OUTDIM 10

#define SROW 136                       // smem row stride in halves (128 + 8 pad)
#define TILE_HALVES (128 * SROW)       // 17408 halves = 34816 B
#define SMEM_G (3 * TILE_HALVES * 2)   // Ahi + Whi + Wlo = 104448 B

// ---------------- device scratch ----------------
__device__ int   g_counts[MAXN];
__device__ int   g_rowptr[MAXN + 1];
__device__ int   g_woff[MAXN];
__device__ int   g_srcidx[MAXET];
__device__ int   g_bnode[MAXN];
__device__ __align__(16) float g_asrc[MAXN * NHEAD];
__device__ __align__(16) float g_adst[MAXN * NHEAD];
__device__ __half2 g_Hh[MAXN * (HCDIM / 2)];        // GEMM out (gather src)
__device__ __half2 g_Hio[2][MAXN * (HCDIM / 2)];    // layer io
__device__ __half2 g_xhi[MAXN * (HCDIM / 2)];       // fp16(x)
__device__ __align__(16) __half g_Whi[3][HCDIM * HCDIM];
__device__ __align__(16) __half g_Wlo[3][HCDIM * HCDIM];
__device__ int   g_bsums[128];

// ---------------- dtype detection helpers ----------------
__device__ __forceinline__ bool edge_is64(const void* edge, long long N) {
    const long long* p = (const long long*)edge;
    int lane = threadIdx.x & 31;
    long long v0 = p[lane];
    long long v1 = p[lane + 32];
    bool bad = (v0 < 0) | (v0 >= N) | (v1 < 0) | (v1 >= N);
    return __all_sync(0xffffffffu, !bad);
}
__device__ __forceinline__ bool batch_is64(const void* batch, int N) {
    const long long* p = (const long long*)batch;
    int lane = threadIdx.x & 31;
    int idx = N / 2 - 1 - lane;
    long long v = (idx >= 0) ? p[idx] : 0;
    bool bad = (v < 0) | (v >= 64);
    return __all_sync(0xffffffffu, !bad);
}

// ---------------- fused prep: W split + x fp16 + node init ----------------
__global__ void prep_all(const float* __restrict__ x,
                         const float* __restrict__ w0,
                         const float* __restrict__ w1,
                         const float* __restrict__ w2, int N) {
    int idx = blockIdx.x * blockDim.x + threadIdx.x;
    if (idx < 3 * HCDIM * HCDIM) {
        int m = idx >> 14;
        int r = idx & 16383;
        const float* w = (m == 0) ? w0 : (m == 1) ? w1 : w2;
        float v = w[r];
        __half hi = __float2half_rn(v);
        g_Whi[m][r] = hi;
        g_Wlo[m][r] = __float2half_rn(v - __half2float(hi));
    }
    if (idx < N * 32) {
        float4 v = ((const float4*)x)[idx];
        __half2 hiA = __floats2half2_rn(v.x, v.y);
        __half2 hiB = __floats2half2_rn(v.z, v.w);
        uint2 sh;
        sh.x = *(const uint32_t*)&hiA;  sh.y = *(const uint32_t*)&hiB;
        ((uint2*)g_xhi)[idx] = sh;
    }
}

// node init (counts seed + batch convert): head of the CSR chain
__global__ void init_node(const void* batch, int N) {
    bool b64 = batch_is64(batch, N);
    int i = blockIdx.x * blockDim.x + threadIdx.x;
    if (i >= N) return;
    g_counts[i] = 1;
    g_bnode[i] = b64 ? (int)((const long long*)batch)[i]
                     : ((const int*)batch)[i];
}

// histogram over dst, 4 edges/thread, vector loads
__global__ void hist_kernel(const void* edge, int E, int N) {
    bool e64 = edge_is64(edge, (long long)N);
    int base = (blockIdx.x * blockDim.x + threadIdx.x) * 4;
    if (base >= E) return;
    int n = min(4, E - base);
    int dd[4];
    if (e64) {
        const long long* p = (const long long*)edge + E;
        if (n == 4 && (((E + base) & 1) == 0)) {
            longlong2 v0 = *(const longlong2*)(p + base);
            longlong2 v1 = *(const longlong2*)(p + base + 2);
            dd[0] = (int)v0.x; dd[1] = (int)v0.y;
            dd[2] = (int)v1.x; dd[3] = (int)v1.y;
        } else {
            for (int j = 0; j < n; j++) dd[j] = (int)p[base + j];
        }
    } else {
        const int* p = (const int*)edge + E;
        if (n == 4 && (((E + base) & 3) == 0)) {
            int4 v = *(const int4*)(p + base);
            dd[0] = v.x; dd[1] = v.y; dd[2] = v.z; dd[3] = v.w;
        } else {
            for (int j = 0; j < n; j++) dd[j] = p[base + j];
        }
    }
    for (int j = 0; j < n; j++) atomicAdd(&g_counts[dd[j]], 1);
}

__global__ void scan_block(int N) {
    __shared__ int sh[1024];
    int i = blockIdx.x * 1024 + threadIdx.x;
    int v = (i < N) ? g_counts[i] : 0;
    sh[threadIdx.x] = v;
    __syncthreads();
    for (int off = 1; off < 1024; off <<= 1) {
        int x = 0;
        if (threadIdx.x >= off) x = sh[threadIdx.x - off];
        __syncthreads();
        if (threadIdx.x >= off) sh[threadIdx.x] += x;
        __syncthreads();
    }
    if (i < N) g_rowptr[i] = sh[threadIdx.x] - v;
    if (threadIdx.x == 1023) g_bsums[blockIdx.x] = sh[1023];
}

// block offset via warp-parallel reduce
__global__ void scan_add2(int N, int total) {
    __shared__ int off0;
    int chunk = (blockIdx.x * blockDim.x) >> 10;
    if (threadIdx.x < 32) {
        int acc = 0;
        for (int b = (int)threadIdx.x; b < chunk; b += 32) acc += g_bsums[b];
        for (int off = 16; off > 0; off >>= 1)
            acc += __shfl_xor_sync(0xffffffffu, acc, off);
        if (threadIdx.x == 0) off0 = acc;
    }
    __syncthreads();
    int i = blockIdx.x * blockDim.x + threadIdx.x;
    if (i < N) {
        int r = g_rowptr[i] + off0;
        g_rowptr[i] = r;
        g_woff[i] = r;
    }
    if (i == 0) g_rowptr[N] = total;
}

// scatter: 4 edges/thread with vector loads, then self-loops
__global__ void scatter_kernel(const void* edge, int E, int N) {
    bool e64 = edge_is64(edge, (long long)N);
    int E4 = (E + 3) >> 2;
    int i = blockIdx.x * blockDim.x + threadIdx.x;
    if (i < E4) {
        int base = i * 4;
        int n = min(4, E - base);
        int ss[4], dd[4];
        if (e64) {
            const long long* p = (const long long*)edge;
            if (n == 4 && ((base & 1) == 0) && (((E + base) & 1) == 0)) {
                longlong2 s0 = *(const longlong2*)(p + base);
                longlong2 s1 = *(const longlong2*)(p + base + 2);
                longlong2 d0 = *(const longlong2*)(p + E + base);
                longlong2 d1 = *(const longlong2*)(p + E + base + 2);
                ss[0] = (int)s0.x; ss[1] = (int)s0.y;
                ss[2] = (int)s1.x; ss[3] = (int)s1.y;
                dd[0] = (int)d0.x; dd[1] = (int)d0.y;
                dd[2] = (int)d1.x; dd[3] = (int)d1.y;
            } else {
                for (int j = 0; j < n; j++) {
                    ss[j] = (int)p[base + j];
                    dd[j] = (int)p[E + base + j];
                }
            }
        } else {
            const int* p = (const int*)edge;
            if (n == 4 && ((base & 3) == 0) && (((E + base) & 3) == 0)) {
                int4 s = *(const int4*)(p + base);
                int4 d = *(const int4*)(p + E + base);
                ss[0] = s.x; ss[1] = s.y; ss[2] = s.z; ss[3] = s.w;
                dd[0] = d.x; dd[1] = d.y; dd[2] = d.z; dd[3] = d.w;
            } else {
                for (int j = 0; j < n; j++) {
                    ss[j] = p[base + j];
                    dd[j] = p[E + base + j];
                }
            }
        }
        for (int j = 0; j < n; j++) {
            int pos = atomicAdd(&g_woff[dd[j]], 1);
            g_srcidx[pos] = ss[j];
        }
    } else {
        int nidx = i - E4;
        if (nidx < N) {
            int pos = atomicAdd(&g_woff[nidx], 1);
            g_srcidx[pos] = nidx;
        }
    }
}

// ---------------- tensor-core helpers ----------------
__device__ __forceinline__ uint32_t sptr(const void* p) {
    return (uint32_t)__cvta_generic_to_shared(p);
}
__device__ __forceinline__ void ldsm4(uint32_t* r, uint32_t a) {
    asm volatile("ldmatrix.sync.aligned.m8n8.x4.shared.b16 {%0,%1,%2,%3}, [%4];"
                 : "=r"(r[0]), "=r"(r[1]), "=r"(r[2]), "=r"(r[3]) : "r"(a));
}
__device__ __forceinline__ void ldsm4t(uint32_t* r, uint32_t a) {
    asm volatile("ldmatrix.sync.aligned.m8n8.x4.trans.shared.b16 {%0,%1,%2,%3}, [%4];"
                 : "=r"(r[0]), "=r"(r[1]), "=r"(r[2]), "=r"(r[3]) : "r"(a));
}
__device__ __forceinline__ void mma16816(float* c, const uint32_t* a, const uint32_t* b) {
    asm volatile("mma.sync.aligned.m16n8k16.row.col.f32.f16.f16.f32 "
                 "{%0,%1,%2,%3}, {%4,%5,%6,%7}, {%8,%9}, {%0,%1,%2,%3};"
                 : "+f"(c[0]), "+f"(c[1]), "+f"(c[2]), "+f"(c[3])
                 : "r"(a[0]), "r"(a[1]), "r"(a[2]), "r"(a[3]),
                   "r"(b[0]), "r"(b[1]));
}

// ---------------- GEMM: 128x128 CTA, warp tile 64Mx32N (1 head/warp) -------
// abuf: -1 -> g_xhi (layer 0), else g_Hio[abuf]. 2 MMA terms (Whi + Wlo).
__global__ void __launch_bounds__(256)
gemm_tc(int abuf, int widx, int M,
        const float* __restrict__ asv, const float* __restrict__ adv) {
    extern __shared__ __half smem[];
    __half* sAhi = smem;
    __half* sWhi = smem + TILE_HALVES;
    __half* sWlo = smem + 2 * TILE_HALVES;

    const __half2* Ahi_g = (abuf < 0) ? g_xhi : g_Hio[abuf];

    const int tid = threadIdx.x;
    const int wid = tid >> 5;
    const int lane = tid & 31;
    const int warp_m = wid & 1;        // 2 warps along M (64 rows each)
    const int warp_n = wid >> 1;       // 4 warps along N (32 cols = 1 head)
    const int bm = blockIdx.x * 128;

    const uint4* wh = (const uint4*)g_Whi[widx];
    const uint4* wl = (const uint4*)g_Wlo[widx];
#pragma unroll
    for (int it = 0; it < 8; it++) {
        int flat = tid + it * 256;
        int row = flat >> 4, q = flat & 15;
        *(uint4*)(sWhi + row * SROW + q * 8) = wh[flat];
        *(uint4*)(sWlo + row * SROW + q * 8) = wl[flat];
    }
#pragma unroll
    for (int it = 0; it < 8; it++) {
        int flat = tid + it * 256;
        int row = flat >> 4, q = flat & 15;
        int grow = bm + row;
        uint4 u = make_uint4(0u, 0u, 0u, 0u);
        if (grow < M) u = ((const uint4*)Ahi_g)[grow * 16 + q];
        *(uint4*)(sAhi + row * SROW + q * 8) = u;
    }
    __syncthreads();

    float acc[4][4][4];                // [mt 16-row][nt 8-col][frag]
#pragma unroll
    for (int mt = 0; mt < 4; mt++)
#pragma unroll
        for (int nt = 0; nt < 4; nt++)
#pragma unroll
            for (int v = 0; v < 4; v++) acc[mt][nt][v] = 0.f;

    uint32_t aHiAddr[4];
#pragma unroll
    for (int mt = 0; mt < 4; mt++) {
        int r = warp_m * 64 + mt * 16 + (lane & 15);
        int c = (lane >> 4) * 8;
        aHiAddr[mt] = sptr(sAhi + r * SROW + c);
    }
    uint32_t wHiAddr[2], wLoAddr[2];
#pragma unroll
    for (int p = 0; p < 2; p++) {
        int kr = (lane & 15);
        int c = warp_n * 32 + p * 16 + (lane >> 4) * 8;
        wHiAddr[p] = sptr(sWhi + kr * SROW + c);
        wLoAddr[p] = sptr(sWlo + kr * SROW + c);
    }

#pragma unroll
    for (int ks = 0; ks < 8; ks++) {
        uint32_t a_hi[4][4];
#pragma unroll
        for (int mt = 0; mt < 4; mt++)
            ldsm4(a_hi[mt], aHiAddr[mt] + ks * 32);
#pragma unroll
        for (int p = 0; p < 2; p++) {
            uint32_t bh[4], bl[4];
            ldsm4t(bh, wHiAddr[p] + ks * 16 * (SROW * 2));
            ldsm4t(bl, wLoAddr[p] + ks * 16 * (SROW * 2));
#pragma unroll
            for (int mt = 0; mt < 4; mt++) {
                mma16816(acc[mt][2 * p], a_hi[mt], bh);
                mma16816(acc[mt][2 * p], a_hi[mt], bl);
                mma16816(acc[mt][2 * p + 1], a_hi[mt], bh + 2);
                mma16816(acc[mt][2 * p + 1], a_hi[mt], bl + 2);
            }
        }
    }

    // ---------- epilogue: fp16 Hh store + fused alpha dots (1 head/warp) ----
    float as_v[4][2], ad_v[4][2];
#pragma unroll
    for (int nt = 0; nt < 4; nt++) {
        int col = warp_n * 32 + nt * 8 + (lane & 3) * 2;
        as_v[nt][0] = asv[col];     as_v[nt][1] = asv[col + 1];
        ad_v[nt][0] = adv[col];     ad_v[nt][1] = adv[col + 1];
    }
#pragma unroll
    for (int mt = 0; mt < 4; mt++) {
#pragma unroll
        for (int half = 0; half < 2; half++) {
            int row = bm + warp_m * 64 + mt * 16 + half * 8 + (lane >> 2);
            float ps = 0.f, pd = 0.f;
#pragma unroll
            for (int nt = 0; nt < 4; nt++) {
                float d0 = acc[mt][nt][half * 2], d1 = acc[mt][nt][half * 2 + 1];
                ps += d0 * as_v[nt][0] + d1 * as_v[nt][1];
                pd += d0 * ad_v[nt][0] + d1 * ad_v[nt][1];
            }
#pragma unroll
            for (int off = 1; off <= 2; off <<= 1) {
                ps += __shfl_xor_sync(0xffffffffu, ps, off);
                pd += __shfl_xor_sync(0xffffffffu, pd, off);
            }
            if ((lane & 3) == 0 && row < M) {
                g_asrc[row * 4 + warp_n] = ps;
                g_adst[row * 4 + warp_n] = pd;
            }
            if (row < M) {
#pragma unroll
                for (int nt = 0; nt < 4; nt++) {
                    int col = warp_n * 32 + nt * 8 + (lane & 3) * 2;
                    g_Hh[row * 64 + (col >> 1)] =
                        __floats2half2_rn(acc[mt][nt][half * 2],
                                          acc[mt][nt][half * 2 + 1]);
                }
            }
        }
    }
}

// ------- agg: smem-broadcast two-phase; phase2 = 2 edges/iter, LDG.128 -----
__global__ void __launch_bounds__(256)
agg_kernel(const float* __restrict__ bias, int outbuf, int Nn) {
    __shared__ int   sh_s[8][32];
    __shared__ float sh_p[8][32][4];
    int w = threadIdx.x >> 5;
    int gwarp = (blockIdx.x * blockDim.x + threadIdx.x) >> 5;
    int lane = threadIdx.x & 31;
    if (gwarp >= Nn) return;
    const float4* asrc4 = (const float4*)g_asrc;
    __half2* Out = g_Hio[outbuf];
    int d = gwarp;
    int j0 = g_rowptr[d];
    int j1 = g_rowptr[d + 1];
    int sub = lane & 15;
    int eh  = lane >> 4;
    int head = sub >> 2;

    float4 adv = ((const float4*)g_adst)[d];

    float acc[8];
#pragma unroll
    for (int i = 0; i < 8; i++) acc[i] = 0.f;
    float psum[NHEAD] = {0.f, 0.f, 0.f, 0.f};

    for (int base = j0; base < j1; base += 32) {
        int j = base + lane;
        if (j < j1) {
            int s = g_srcidx[j];
            float4 av = asrc4[s];
            float e0 = av.x + adv.x; e0 = (e0 > 0.f) ? e0 : 0.2f * e0;
            float e1 = av.y + adv.y; e1 = (e1 > 0.f) ? e1 : 0.2f * e1;
            float e2 = av.z + adv.z; e2 = (e2 > 0.f) ? e2 : 0.2f * e2;
            float e3 = av.w + adv.w; e3 = (e3 > 0.f) ? e3 : 0.2f * e3;
            float p0 = __expf(e0), p1 = __expf(e1);
            float p2 = __expf(e2), p3 = __expf(e3);
            psum[0] += p0; psum[1] += p1; psum[2] += p2; psum[3] += p3;
            sh_s[w][lane] = s;
            *(float4*)&sh_p[w][lane][0] = make_float4(p0, p1, p2, p3);
        }
        __syncwarp();
        int cnt = min(32, j1 - base);
#pragma unroll 4
        for (int k = 0; k < cnt; k += 2) {
            int kk = k + eh;
            float pk = 0.f;
            int sk = sh_s[w][k];
            if (kk < cnt) { sk = sh_s[w][kk]; pk = sh_p[w][kk][head]; }
            uint4 u = __ldg(&((const uint4*)(g_Hh + sk * 64))[sub]);
            float2 f0 = __half22float2(*(const __half2*)&u.x);
            float2 f1 = __half22float2(*(const __half2*)&u.y);
            float2 f2 = __half22float2(*(const __half2*)&u.z);
            float2 f3 = __half22float2(*(const __half2*)&u.w);
            acc[0] += pk * f0.x; acc[1] += pk * f0.y;
            acc[2] += pk * f1.x; acc[3] += pk * f1.y;
            acc[4] += pk * f2.x; acc[5] += pk * f2.y;
            acc[6] += pk * f3.x; acc[7] += pk * f3.y;
        }
        __syncwarp();
    }
#pragma unroll
    for (int i = 0; i < 8; i++)
        acc[i] += __shfl_xor_sync(0xffffffffu, acc[i], 16);
#pragma unroll
    for (int h = 0; h < NHEAD; h++)
        for (int off = 16; off > 0; off >>= 1)
            psum[h] += __shfl_xor_sync(0xffffffffu, psum[h], off);

    if (eh == 0) {
        float pd = (head == 0) ? psum[0] : (head == 1) ? psum[1]
                 : (head == 2) ? psum[2] : psum[3];
        float rinv = 1.0f / pd;
        float4 b0 = *(const float4*)(bias + sub * 8);
        float4 b1 = *(const float4*)(bias + sub * 8 + 4);
        __half2 h0 = __floats2half2_rn(fmaxf(acc[0] * rinv + b0.x, 0.f),
                                       fmaxf(acc[1] * rinv + b0.y, 0.f));
        __half2 h1 = __floats2half2_rn(fmaxf(acc[2] * rinv + b0.z, 0.f),
                                       fmaxf(acc[3] * rinv + b0.w, 0.f));
        __half2 h2 = __floats2half2_rn(fmaxf(acc[4] * rinv + b1.x, 0.f),
                                       fmaxf(acc[5] * rinv + b1.y, 0.f));
        __half2 h3 = __floats2half2_rn(fmaxf(acc[6] * rinv + b1.z, 0.f),
                                       fmaxf(acc[7] * rinv + b1.w, 0.f));
        uint4 st;
        st.x = *(const uint32_t*)&h0;
        st.y = *(const uint32_t*)&h1;
        st.z = *(const uint32_t*)&h2;
        st.w = *(const uint32_t*)&h3;
        ((uint4*)(Out + d * 64))[sub] = st;
    }
}

// ---------------- fused pool (block/graph, batch sorted) + MLP --------------
__device__ __forceinline__ int lower_bound_dev(const int* a, int n, int v) {
    int lo = 0, hi = n;
    while (lo < hi) { int m = (lo + hi) >> 1; if (a[m] < v) lo = m + 1; else hi = m; }
    return lo;
}

__global__ void pool_mlp_kernel(int inbuf, int Nn,
                                const float* __restrict__ Wlin,
                                const float* __restrict__ blin,
                                const float* __restrict__ Wout,
                                const float* __restrict__ bout,
                                float* __restrict__ out) {
    __shared__ float pooled[HCDIM];
    __shared__ float z[LINDIM];
    __shared__ int srange[2];
    int g = blockIdx.x;
    int t = threadIdx.x;
    if (t < 2) srange[t] = lower_bound_dev(g_bnode, Nn, g + t);
    __syncthreads();
    int s0 = srange[0], s1 = srange[1];
    if (t < HCDIM) {
        const __half* Hf = (const __half*)g_Hio[inbuf];
        float m = 0.f;
        for (int n = s0; n < s1; n++)
            m = fmaxf(m, __half2float(Hf[n * HCDIM + t]));
        pooled[t] = m;
    }
    __syncthreads();
    {
        float acc = blin[t];
#pragma unroll 8
        for (int k = 0; k < HCDIM; k++)
            acc += pooled[k] * Wlin[k * LINDIM + t];
        z[t] = acc;
    }
    __syncthreads();
    if (t < OUTDIM) {
        float acc = bout[t];
#pragma unroll 8
        for (int k = 0; k < LINDIM; k++)
            acc += z[k] * Wout[k * OUTDIM + t];
        out[g * OUTDIM + t] = acc;
    }
}

// ---------------- launcher ----------------
extern "C" void kernel_launch(void* const* d_in, const int* in_sizes, int n_in,
                              void* d_out, int out_size) {
    const float* x     = (const float*)d_in[0];
    const void*  edge  = d_in[1];
    const void*  batch = d_in[2];
    const float* W0 = (const float*)d_in[3];
    const float* as0 = (const float*)d_in[4];
    const float* ad0 = (const float*)d_in[5];
    const float* b0 = (const float*)d_in[6];
    const float* W1 = (const float*)d_in[7];
    const float* as1 = (const float*)d_in[8];
    const float* ad1 = (const float*)d_in[9];
    const float* b1 = (const float*)d_in[10];
    const float* W2 = (const float*)d_in[11];
    const float* as2 = (const float*)d_in[12];
    const float* ad2 = (const float*)d_in[13];
    const float* b2 = (const float*)d_in[14];
    const float* Wlin = (const float*)d_in[15];
    const float* blin = (const float*)d_in[16];
    const float* Wout = (const float*)d_in[17];
    const float* bout = (const float*)d_in[18];
    float* out = (float*)d_out;

    int N = in_sizes[0] / HCDIM;
    int E = in_sizes[1] / 2;

    cudaFuncSetAttribute(gemm_tc,
                         cudaFuncAttributeMaxDynamicSharedMemorySize, SMEM_G);

    // two created side streams (host-side resources only; created once)
    static cudaStream_t s1 = nullptr, s2 = nullptr;
    static cudaEvent_t evFork = nullptr, evJ1 = nullptr, evJ2 = nullptr;
    if (s1 == nullptr) {
        cudaStreamCreateWithFlags(&s1, cudaStreamNonBlocking);
        cudaStreamCreateWithFlags(&s2, cudaStreamNonBlocking);
        cudaEventCreateWithFlags(&evFork, cudaEventDisableTiming);
        cudaEventCreateWithFlags(&evJ1, cudaEventDisableTiming);
        cudaEventCreateWithFlags(&evJ2, cudaEventDisableTiming);
    }

    int MB = (N + 127) / 128;
    int aggBlocks = (N * 32 + 255) / 256;
    int NB = (N + 1023) / 1024;
    int E4 = (E + 3) / 4;

    // fork from the capture (default) stream into two created streams
    cudaEventRecord(evFork, 0);
    cudaStreamWaitEvent(s1, evFork, 0);
    cudaStreamWaitEvent(s2, evFork, 0);

    // branch 1: prep + layer-0 GEMM
    prep_all<<<(N * 32 + 255) / 256, 256, 0, s1>>>(x, W0, W1, W2, N);
    gemm_tc<<<MB, 256, SMEM_G, s1>>>(-1, 0, N, as0, ad0);
    cudaEventRecord(evJ1, s1);

    // branch 2: CSR build
    init_node<<<(N + 255) / 256, 256, 0, s2>>>(batch, N);
    hist_kernel<<<(E4 + 255) / 256, 256, 0, s2>>>(edge, E, N);
    scan_block<<<NB, 1024, 0, s2>>>(N);
    scan_add2<<<(N + 255) / 256, 256, 0, s2>>>(N, E + N);
    scatter_kernel<<<(E4 + N + 255) / 256, 256, 0, s2>>>(edge, E, N);
    cudaEventRecord(evJ2, s2);

    // join both branches back into the default stream
    cudaStreamWaitEvent(0, evJ1, 0);
    cudaStreamWaitEvent(0, evJ2, 0);

    agg_kernel<<<aggBlocks, 256>>>(b0, 0, N);
    gemm_tc<<<MB, 256, SMEM_G>>>(0, 1, N, as1, ad1);
    agg_kernel<<<aggBlocks, 256>>>(b1, 1, N);
    gemm_tc<<<MB, 256, SMEM_G>>>(1, 2, N, as2, ad2);
    agg_kernel<<<aggBlocks, 256>>>(b2, 0, N);

    pool_mlp_kernel<<<GN, LINDIM>>>(0, N, Wlin, blin, Wout, bout, out);
}

// round 17
// speedup vs baseline: 1.0921x; 1.0097x over previous
#include <cuda_runtime.h>
#include <cuda_fp16.h>
#include <stdint.h>
#include <math.h>

#define MAXN 50016
#define MAXE 800000
#define MAXET (MAXE + MAXN)
#define HCDIM 128
#define NHEAD 4
#define GN 64
#define LINDIM 256
#define OUTDIM 10

#define SROW 136                       // smem row stride in halves (128 + 8 pad)
#define TILE_HALVES (128 * SROW)       // 17408 halves = 34816 B
#define SMEM_G (3 * TILE_HALVES * 2)   // Ahi + Whi + Wlo = 104448 B

// ---------------- device scratch ----------------
__device__ int   g_counts[MAXN];
__device__ int   g_rowptr[MAXN + 1];
__device__ int   g_woff[MAXN];
__device__ int   g_srcidx[MAXET];
__device__ int   g_bnode[MAXN];
__device__ __align__(16) float g_asrc[MAXN * NHEAD];
__device__ __align__(16) float g_adst[MAXN * NHEAD];
__device__ __half2 g_Hh[MAXN * (HCDIM / 2)];        // GEMM out (gather src)
__device__ __half2 g_Hio[2][MAXN * (HCDIM / 2)];    // layer io
__device__ __half2 g_xhi[MAXN * (HCDIM / 2)];       // fp16(x)
__device__ __align__(16) __half g_Whi[3][HCDIM * HCDIM];
__device__ __align__(16) __half g_Wlo[3][HCDIM * HCDIM];
__device__ int   g_bsums[128];

// ---------------- dtype detection helpers ----------------
__device__ __forceinline__ bool edge_is64(const void* edge, long long N) {
    const long long* p = (const long long*)edge;
    int lane = threadIdx.x & 31;
    long long v0 = p[lane];
    long long v1 = p[lane + 32];
    bool bad = (v0 < 0) | (v0 >= N) | (v1 < 0) | (v1 >= N);
    return __all_sync(0xffffffffu, !bad);
}
__device__ __forceinline__ bool batch_is64(const void* batch, int N) {
    const long long* p = (const long long*)batch;
    int lane = threadIdx.x & 31;
    int idx = N / 2 - 1 - lane;
    long long v = (idx >= 0) ? p[idx] : 0;
    bool bad = (v < 0) | (v >= 64);
    return __all_sync(0xffffffffu, !bad);
}

// ---------------- prep: W split + x fp16 (branch 1) ----------------
__global__ void prep_all(const float* __restrict__ x,
                         const float* __restrict__ w0,
                         const float* __restrict__ w1,
                         const float* __restrict__ w2, int N) {
    int idx = blockIdx.x * blockDim.x + threadIdx.x;
    if (idx < 3 * HCDIM * HCDIM) {
        int m = idx >> 14;
        int r = idx & 16383;
        const float* w = (m == 0) ? w0 : (m == 1) ? w1 : w2;
        float v = w[r];
        __half hi = __float2half_rn(v);
        g_Whi[m][r] = hi;
        g_Wlo[m][r] = __float2half_rn(v - __half2float(hi));
    }
    if (idx < N * 32) {
        float4 v = ((const float4*)x)[idx];
        __half2 hiA = __floats2half2_rn(v.x, v.y);
        __half2 hiB = __floats2half2_rn(v.z, v.w);
        uint2 sh;
        sh.x = *(const uint32_t*)&hiA;  sh.y = *(const uint32_t*)&hiB;
        ((uint2*)g_xhi)[idx] = sh;
    }
}

// histogram over dst, 8 edges/thread (counts zeroed via memset; +1 self-loop
// is applied in scan_block)
__global__ void hist_kernel(const void* edge, int E, int N) {
    bool e64 = edge_is64(edge, (long long)N);
    int base = (blockIdx.x * blockDim.x + threadIdx.x) * 8;
    if (base >= E) return;
    int n = min(8, E - base);
    int dd[8];
    if (e64) {
        const long long* p = (const long long*)edge + E;
        if (n == 8 && (((E + base) & 1) == 0)) {
#pragma unroll
            for (int q = 0; q < 4; q++) {
                longlong2 v = *(const longlong2*)(p + base + 2 * q);
                dd[2 * q] = (int)v.x; dd[2 * q + 1] = (int)v.y;
            }
        } else {
            for (int j = 0; j < n; j++) dd[j] = (int)p[base + j];
        }
    } else {
        const int* p = (const int*)edge + E;
        if (n == 8 && (((E + base) & 3) == 0)) {
            int4 v0 = *(const int4*)(p + base);
            int4 v1 = *(const int4*)(p + base + 4);
            dd[0] = v0.x; dd[1] = v0.y; dd[2] = v0.z; dd[3] = v0.w;
            dd[4] = v1.x; dd[5] = v1.y; dd[6] = v1.z; dd[7] = v1.w;
        } else {
            for (int j = 0; j < n; j++) dd[j] = p[base + j];
        }
    }
    for (int j = 0; j < n; j++) atomicAdd(&g_counts[dd[j]], 1);
}

// block scan; +1 per node = self-loop
__global__ void scan_block(int N) {
    __shared__ int sh[1024];
    int i = blockIdx.x * 1024 + threadIdx.x;
    int v = (i < N) ? (g_counts[i] + 1) : 0;
    sh[threadIdx.x] = v;
    __syncthreads();
    for (int off = 1; off < 1024; off <<= 1) {
        int x = 0;
        if (threadIdx.x >= off) x = sh[threadIdx.x - off];
        __syncthreads();
        if (threadIdx.x >= off) sh[threadIdx.x] += x;
        __syncthreads();
    }
    if (i < N) g_rowptr[i] = sh[threadIdx.x] - v;
    if (threadIdx.x == 1023) g_bsums[blockIdx.x] = sh[1023];
}

// block offset (warp-parallel) + batch convert folded in
__global__ void scan_add2(const void* batch, int N, int total) {
    __shared__ int off0;
    bool b64 = batch_is64(batch, N);
    int chunk = (blockIdx.x * blockDim.x) >> 10;
    if (threadIdx.x < 32) {
        int acc = 0;
        for (int b = (int)threadIdx.x; b < chunk; b += 32) acc += g_bsums[b];
        for (int off = 16; off > 0; off >>= 1)
            acc += __shfl_xor_sync(0xffffffffu, acc, off);
        if (threadIdx.x == 0) off0 = acc;
    }
    __syncthreads();
    int i = blockIdx.x * blockDim.x + threadIdx.x;
    if (i < N) {
        int r = g_rowptr[i] + off0;
        g_rowptr[i] = r;
        g_woff[i] = r;
        g_bnode[i] = b64 ? (int)((const long long*)batch)[i]
                         : ((const int*)batch)[i];
    }
    if (i == 0) g_rowptr[N] = total;
}

// scatter: 8 edges/thread, then self-loops
__global__ void scatter_kernel(const void* edge, int E, int N) {
    bool e64 = edge_is64(edge, (long long)N);
    int E8 = (E + 7) >> 3;
    int i = blockIdx.x * blockDim.x + threadIdx.x;
    if (i < E8) {
        int base = i * 8;
        int n = min(8, E - base);
        int ss[8], dd[8];
        if (e64) {
            const long long* p = (const long long*)edge;
            if (n == 8 && ((base & 1) == 0) && (((E + base) & 1) == 0)) {
#pragma unroll
                for (int q = 0; q < 4; q++) {
                    longlong2 s = *(const longlong2*)(p + base + 2 * q);
                    longlong2 d = *(const longlong2*)(p + E + base + 2 * q);
                    ss[2 * q] = (int)s.x; ss[2 * q + 1] = (int)s.y;
                    dd[2 * q] = (int)d.x; dd[2 * q + 1] = (int)d.y;
                }
            } else {
                for (int j = 0; j < n; j++) {
                    ss[j] = (int)p[base + j];
                    dd[j] = (int)p[E + base + j];
                }
            }
        } else {
            const int* p = (const int*)edge;
            if (n == 8 && ((base & 3) == 0) && (((E + base) & 3) == 0)) {
                int4 s0 = *(const int4*)(p + base);
                int4 s1 = *(const int4*)(p + base + 4);
                int4 d0 = *(const int4*)(p + E + base);
                int4 d1 = *(const int4*)(p + E + base + 4);
                ss[0] = s0.x; ss[1] = s0.y; ss[2] = s0.z; ss[3] = s0.w;
                ss[4] = s1.x; ss[5] = s1.y; ss[6] = s1.z; ss[7] = s1.w;
                dd[0] = d0.x; dd[1] = d0.y; dd[2] = d0.z; dd[3] = d0.w;
                dd[4] = d1.x; dd[5] = d1.y; dd[6] = d1.z; dd[7] = d1.w;
            } else {
                for (int j = 0; j < n; j++) {
                    ss[j] = p[base + j];
                    dd[j] = p[E + base + j];
                }
            }
        }
        for (int j = 0; j < n; j++) {
            int pos = atomicAdd(&g_woff[dd[j]], 1);
            g_srcidx[pos] = ss[j];
        }
    } else {
        int nidx = i - E8;
        if (nidx < N) {
            int pos = atomicAdd(&g_woff[nidx], 1);
            g_srcidx[pos] = nidx;
        }
    }
}

// ---------------- tensor-core helpers ----------------
__device__ __forceinline__ uint32_t sptr(const void* p) {
    return (uint32_t)__cvta_generic_to_shared(p);
}
__device__ __forceinline__ void ldsm4(uint32_t* r, uint32_t a) {
    asm volatile("ldmatrix.sync.aligned.m8n8.x4.shared.b16 {%0,%1,%2,%3}, [%4];"
                 : "=r"(r[0]), "=r"(r[1]), "=r"(r[2]), "=r"(r[3]) : "r"(a));
}
__device__ __forceinline__ void ldsm4t(uint32_t* r, uint32_t a) {
    asm volatile("ldmatrix.sync.aligned.m8n8.x4.trans.shared.b16 {%0,%1,%2,%3}, [%4];"
                 : "=r"(r[0]), "=r"(r[1]), "=r"(r[2]), "=r"(r[3]) : "r"(a));
}
__device__ __forceinline__ void mma16816(float* c, const uint32_t* a, const uint32_t* b) {
    asm volatile("mma.sync.aligned.m16n8k16.row.col.f32.f16.f16.f32 "
                 "{%0,%1,%2,%3}, {%4,%5,%6,%7}, {%8,%9}, {%0,%1,%2,%3};"
                 : "+f"(c[0]), "+f"(c[1]), "+f"(c[2]), "+f"(c[3])
                 : "r"(a[0]), "r"(a[1]), "r"(a[2]), "r"(a[3]),
                   "r"(b[0]), "r"(b[1]));
}

// ---------------- GEMM: 128x128 CTA, warp tile 64Mx32N (1 head/warp) -------
__global__ void __launch_bounds__(256)
gemm_tc(int abuf, int widx, int M,
        const float* __restrict__ asv, const float* __restrict__ adv) {
    extern __shared__ __half smem[];
    __half* sAhi = smem;
    __half* sWhi = smem + TILE_HALVES;
    __half* sWlo = smem + 2 * TILE_HALVES;

    const __half2* Ahi_g = (abuf < 0) ? g_xhi : g_Hio[abuf];

    const int tid = threadIdx.x;
    const int wid = tid >> 5;
    const int lane = tid & 31;
    const int warp_m = wid & 1;
    const int warp_n = wid >> 1;
    const int bm = blockIdx.x * 128;

    const uint4* wh = (const uint4*)g_Whi[widx];
    const uint4* wl = (const uint4*)g_Wlo[widx];
#pragma unroll
    for (int it = 0; it < 8; it++) {
        int flat = tid + it * 256;
        int row = flat >> 4, q = flat & 15;
        *(uint4*)(sWhi + row * SROW + q * 8) = wh[flat];
        *(uint4*)(sWlo + row * SROW + q * 8) = wl[flat];
    }
#pragma unroll
    for (int it = 0; it < 8; it++) {
        int flat = tid + it * 256;
        int row = flat >> 4, q = flat & 15;
        int grow = bm + row;
        uint4 u = make_uint4(0u, 0u, 0u, 0u);
        if (grow < M) u = ((const uint4*)Ahi_g)[grow * 16 + q];
        *(uint4*)(sAhi + row * SROW + q * 8) = u;
    }
    __syncthreads();

    float acc[4][4][4];
#pragma unroll
    for (int mt = 0; mt < 4; mt++)
#pragma unroll
        for (int nt = 0; nt < 4; nt++)
#pragma unroll
            for (int v = 0; v < 4; v++) acc[mt][nt][v] = 0.f;

    uint32_t aHiAddr[4];
#pragma unroll
    for (int mt = 0; mt < 4; mt++) {
        int r = warp_m * 64 + mt * 16 + (lane & 15);
        int c = (lane >> 4) * 8;
        aHiAddr[mt] = sptr(sAhi + r * SROW + c);
    }
    uint32_t wHiAddr[2], wLoAddr[2];
#pragma unroll
    for (int p = 0; p < 2; p++) {
        int kr = (lane & 15);
        int c = warp_n * 32 + p * 16 + (lane >> 4) * 8;
        wHiAddr[p] = sptr(sWhi + kr * SROW + c);
        wLoAddr[p] = sptr(sWlo + kr * SROW + c);
    }

#pragma unroll
    for (int ks = 0; ks < 8; ks++) {
        uint32_t a_hi[4][4];
#pragma unroll
        for (int mt = 0; mt < 4; mt++)
            ldsm4(a_hi[mt], aHiAddr[mt] + ks * 32);
#pragma unroll
        for (int p = 0; p < 2; p++) {
            uint32_t bh[4], bl[4];
            ldsm4t(bh, wHiAddr[p] + ks * 16 * (SROW * 2));
            ldsm4t(bl, wLoAddr[p] + ks * 16 * (SROW * 2));
#pragma unroll
            for (int mt = 0; mt < 4; mt++) {
                mma16816(acc[mt][2 * p], a_hi[mt], bh);
                mma16816(acc[mt][2 * p], a_hi[mt], bl);
                mma16816(acc[mt][2 * p + 1], a_hi[mt], bh + 2);
                mma16816(acc[mt][2 * p + 1], a_hi[mt], bl + 2);
            }
        }
    }

    float as_v[4][2], ad_v[4][2];
#pragma unroll
    for (int nt = 0; nt < 4; nt++) {
        int col = warp_n * 32 + nt * 8 + (lane & 3) * 2;
        as_v[nt][0] = asv[col];     as_v[nt][1] = asv[col + 1];
        ad_v[nt][0] = adv[col];     ad_v[nt][1] = adv[col + 1];
    }
#pragma unroll
    for (int mt = 0; mt < 4; mt++) {
#pragma unroll
        for (int half = 0; half < 2; half++) {
            int row = bm + warp_m * 64 + mt * 16 + half * 8 + (lane >> 2);
            float ps = 0.f, pd = 0.f;
#pragma unroll
            for (int nt = 0; nt < 4; nt++) {
                float d0 = acc[mt][nt][half * 2], d1 = acc[mt][nt][half * 2 + 1];
                ps += d0 * as_v[nt][0] + d1 * as_v[nt][1];
                pd += d0 * ad_v[nt][0] + d1 * ad_v[nt][1];
            }
#pragma unroll
            for (int off = 1; off <= 2; off <<= 1) {
                ps += __shfl_xor_sync(0xffffffffu, ps, off);
                pd += __shfl_xor_sync(0xffffffffu, pd, off);
            }
            if ((lane & 3) == 0 && row < M) {
                g_asrc[row * 4 + warp_n] = ps;
                g_adst[row * 4 + warp_n] = pd;
            }
            if (row < M) {
#pragma unroll
                for (int nt = 0; nt < 4; nt++) {
                    int col = warp_n * 32 + nt * 8 + (lane & 3) * 2;
                    g_Hh[row * 64 + (col >> 1)] =
                        __floats2half2_rn(acc[mt][nt][half * 2],
                                          acc[mt][nt][half * 2 + 1]);
                }
            }
        }
    }
}

// ------- agg: smem-broadcast two-phase; phase2 = 2 edges/iter, LDG.128 -----
__global__ void __launch_bounds__(256)
agg_kernel(const float* __restrict__ bias, int outbuf, int Nn) {
    __shared__ int   sh_s[8][32];
    __shared__ float sh_p[8][32][4];
    int w = threadIdx.x >> 5;
    int gwarp = (blockIdx.x * blockDim.x + threadIdx.x) >> 5;
    int lane = threadIdx.x & 31;
    if (gwarp >= Nn) return;
    const float4* asrc4 = (const float4*)g_asrc;
    __half2* Out = g_Hio[outbuf];
    int d = gwarp;
    int j0 = g_rowptr[d];
    int j1 = g_rowptr[d + 1];
    int sub = lane & 15;
    int eh  = lane >> 4;
    int head = sub >> 2;

    float4 adv = ((const float4*)g_adst)[d];

    float acc[8];
#pragma unroll
    for (int i = 0; i < 8; i++) acc[i] = 0.f;
    float psum[NHEAD] = {0.f, 0.f, 0.f, 0.f};

    for (int base = j0; base < j1; base += 32) {
        int j = base + lane;
        if (j < j1) {
            int s = g_srcidx[j];
            float4 av = asrc4[s];
            float e0 = av.x + adv.x; e0 = (e0 > 0.f) ? e0 : 0.2f * e0;
            float e1 = av.y + adv.y; e1 = (e1 > 0.f) ? e1 : 0.2f * e1;
            float e2 = av.z + adv.z; e2 = (e2 > 0.f) ? e2 : 0.2f * e2;
            float e3 = av.w + adv.w; e3 = (e3 > 0.f) ? e3 : 0.2f * e3;
            float p0 = __expf(e0), p1 = __expf(e1);
            float p2 = __expf(e2), p3 = __expf(e3);
            psum[0] += p0; psum[1] += p1; psum[2] += p2; psum[3] += p3;
            sh_s[w][lane] = s;
            *(float4*)&sh_p[w][lane][0] = make_float4(p0, p1, p2, p3);
        }
        __syncwarp();
        int cnt = min(32, j1 - base);
#pragma unroll 4
        for (int k = 0; k < cnt; k += 2) {
            int kk = k + eh;
            float pk = 0.f;
            int sk = sh_s[w][k];
            if (kk < cnt) { sk = sh_s[w][kk]; pk = sh_p[w][kk][head]; }
            uint4 u = __ldg(&((const uint4*)(g_Hh + sk * 64))[sub]);
            float2 f0 = __half22float2(*(const __half2*)&u.x);
            float2 f1 = __half22float2(*(const __half2*)&u.y);
            float2 f2 = __half22float2(*(const __half2*)&u.z);
            float2 f3 = __half22float2(*(const __half2*)&u.w);
            acc[0] += pk * f0.x; acc[1] += pk * f0.y;
            acc[2] += pk * f1.x; acc[3] += pk * f1.y;
            acc[4] += pk * f2.x; acc[5] += pk * f2.y;
            acc[6] += pk * f3.x; acc[7] += pk * f3.y;
        }
        __syncwarp();
    }
#pragma unroll
    for (int i = 0; i < 8; i++)
        acc[i] += __shfl_xor_sync(0xffffffffu, acc[i], 16);
#pragma unroll
    for (int h = 0; h < NHEAD; h++)
        for (int off = 16; off > 0; off >>= 1)
            psum[h] += __shfl_xor_sync(0xffffffffu, psum[h], off);

    if (eh == 0) {
        float pd = (head == 0) ? psum[0] : (head == 1) ? psum[1]
                 : (head == 2) ? psum[2] : psum[3];
        float rinv = 1.0f / pd;
        float4 b0 = *(const float4*)(bias + sub * 8);
        float4 b1 = *(const float4*)(bias + sub * 8 + 4);
        __half2 h0 = __floats2half2_rn(fmaxf(acc[0] * rinv + b0.x, 0.f),
                                       fmaxf(acc[1] * rinv + b0.y, 0.f));
        __half2 h1 = __floats2half2_rn(fmaxf(acc[2] * rinv + b0.z, 0.f),
                                       fmaxf(acc[3] * rinv + b0.w, 0.f));
        __half2 h2 = __floats2half2_rn(fmaxf(acc[4] * rinv + b1.x, 0.f),
                                       fmaxf(acc[5] * rinv + b1.y, 0.f));
        __half2 h3 = __floats2half2_rn(fmaxf(acc[6] * rinv + b1.z, 0.f),
                                       fmaxf(acc[7] * rinv + b1.w, 0.f));
        uint4 st;
        st.x = *(const uint32_t*)&h0;
        st.y = *(const uint32_t*)&h1;
        st.z = *(const uint32_t*)&h2;
        st.w = *(const uint32_t*)&h3;
        ((uint4*)(Out + d * 64))[sub] = st;
    }
}

// ---------------- fused pool (block/graph, batch sorted) + MLP --------------
__device__ __forceinline__ int lower_bound_dev(const int* a, int n, int v) {
    int lo = 0, hi = n;
    while (lo < hi) { int m = (lo + hi) >> 1; if (a[m] < v) lo = m + 1; else hi = m; }
    return lo;
}

__global__ void pool_mlp_kernel(int inbuf, int Nn,
                                const float* __restrict__ Wlin,
                                const float* __restrict__ blin,
                                const float* __restrict__ Wout,
                                const float* __restrict__ bout,
                                float* __restrict__ out) {
    __shared__ float pooled[HCDIM];
    __shared__ float z[LINDIM];
    __shared__ int srange[2];
    int g = blockIdx.x;
    int t = threadIdx.x;
    if (t < 2) srange[t] = lower_bound_dev(g_bnode, Nn, g + t);
    __syncthreads();
    int s0 = srange[0], s1 = srange[1];
    if (t < HCDIM) {
        const __half* Hf = (const __half*)g_Hio[inbuf];
        float m = 0.f;
        for (int n = s0; n < s1; n++)
            m = fmaxf(m, __half2float(Hf[n * HCDIM + t]));
        pooled[t] = m;
    }
    __syncthreads();
    {
        float acc = blin[t];
#pragma unroll 8
        for (int k = 0; k < HCDIM; k++)
            acc += pooled[k] * Wlin[k * LINDIM + t];
        z[t] = acc;
    }
    __syncthreads();
    if (t < OUTDIM) {
        float acc = bout[t];
#pragma unroll 8
        for (int k = 0; k < LINDIM; k++)
            acc += z[k] * Wout[k * OUTDIM + t];
        out[g * OUTDIM + t] = acc;
    }
}

// ---------------- launcher ----------------
extern "C" void kernel_launch(void* const* d_in, const int* in_sizes, int n_in,
                              void* d_out, int out_size) {
    const float* x     = (const float*)d_in[0];
    const void*  edge  = d_in[1];
    const void*  batch = d_in[2];
    const float* W0 = (const float*)d_in[3];
    const float* as0 = (const float*)d_in[4];
    const float* ad0 = (const float*)d_in[5];
    const float* b0 = (const float*)d_in[6];
    const float* W1 = (const float*)d_in[7];
    const float* as1 = (const float*)d_in[8];
    const float* ad1 = (const float*)d_in[9];
    const float* b1 = (const float*)d_in[10];
    const float* W2 = (const float*)d_in[11];
    const float* as2 = (const float*)d_in[12];
    const float* ad2 = (const float*)d_in[13];
    const float* b2 = (const float*)d_in[14];
    const float* Wlin = (const float*)d_in[15];
    const float* blin = (const float*)d_in[16];
    const float* Wout = (const float*)d_in[17];
    const float* bout = (const float*)d_in[18];
    float* out = (float*)d_out;

    int N = in_sizes[0] / HCDIM;
    int E = in_sizes[1] / 2;

    cudaFuncSetAttribute(gemm_tc,
                         cudaFuncAttributeMaxDynamicSharedMemorySize, SMEM_G);

    static cudaStream_t s1 = nullptr, s2 = nullptr;
    static cudaEvent_t evFork = nullptr, evJ1 = nullptr, evJ2 = nullptr;
    static void* countsAddr = nullptr;
    if (s1 == nullptr) {
        cudaStreamCreateWithFlags(&s1, cudaStreamNonBlocking);
        cudaStreamCreateWithFlags(&s2, cudaStreamNonBlocking);
        cudaEventCreateWithFlags(&evFork, cudaEventDisableTiming);
        cudaEventCreateWithFlags(&evJ1, cudaEventDisableTiming);
        cudaEventCreateWithFlags(&evJ2, cudaEventDisableTiming);
        cudaGetSymbolAddress(&countsAddr, g_counts);
    }

    int MB = (N + 127) / 128;
    int aggBlocks = (N * 32 + 255) / 256;
    int NB = (N + 1023) / 1024;
    int E8 = (E + 7) / 8;

    cudaEventRecord(evFork, 0);
    cudaStreamWaitEvent(s1, evFork, 0);
    cudaStreamWaitEvent(s2, evFork, 0);

    // branch 1: prep + layer-0 GEMM
    prep_all<<<(N * 32 + 255) / 256, 256, 0, s1>>>(x, W0, W1, W2, N);
    gemm_tc<<<MB, 256, SMEM_G, s1>>>(-1, 0, N, as0, ad0);
    cudaEventRecord(evJ1, s1);

    // branch 2: CSR build
    cudaMemsetAsync(countsAddr, 0, N * sizeof(int), s2);
    hist_kernel<<<(E8 + 255) / 256, 256, 0, s2>>>(edge, E, N);
    scan_block<<<NB, 1024, 0, s2>>>(N);
    scan_add2<<<(N + 255) / 256, 256, 0, s2>>>(batch, N, E + N);
    scatter_kernel<<<(E8 + N + 255) / 256, 256, 0, s2>>>(edge, E, N);
    cudaEventRecord(evJ2, s2);

    cudaStreamWaitEvent(0, evJ1, 0);
    cudaStreamWaitEvent(0, evJ2, 0);

    agg_kernel<<<aggBlocks, 256>>>(b0, 0, N);
    gemm_tc<<<MB, 256, SMEM_G>>>(0, 1, N, as1, ad1);
    agg_kernel<<<aggBlocks, 256>>>(b1, 1, N);
    gemm_tc<<<MB, 256, SMEM_G>>>(1, 2, N, as2, ad2);
    agg_kernel<<<aggBlocks, 256>>>(b2, 0, N);

    pool_mlp_kernel<<<GN, LINDIM>>>(0, N, Wlin, blin, Wout, bout, out);
}